// round 1
// baseline (speedup 1.0000x reference)
#include <cuda_runtime.h>

// ---------------------------------------------------------------------------
// Problem constants (fixed by the dataset)
// ---------------------------------------------------------------------------
constexpr int BSZ = 2;
constexpr int L   = 2048;
constexpr int DM  = 1024;        // d_model
constexpr int DIN = 2048;        // d_inner
constexpr int NST = 16;          // d_state
constexpr int ROWS = BSZ * L;    // 4096 flattened (b,l) rows
constexpr int NCH  = 16;         // scan chunks
constexpr int LC   = L / NCH;    // 128 steps per chunk

// ---------------------------------------------------------------------------
// Scratch (static device globals -- no runtime allocation allowed)
// ---------------------------------------------------------------------------
__device__ float g_xn   [(size_t)ROWS * DM];        // layernorm output
__device__ float g_xz   [(size_t)ROWS * 2 * DIN];   // in-proj output (x_path | z_path)
__device__ float g_u    [(size_t)ROWS * DIN];       // conv + silu output
__device__ float g_delta[(size_t)ROWS * DIN];       // softplus(u@w_delta + b_delta)
__device__ float g_Bseq [(size_t)ROWS * NST];
__device__ float g_Cseq [(size_t)ROWS * NST];
__device__ float g_gate [(size_t)ROWS * DIN];       // y * silu(z)
__device__ float g_P    [(size_t)BSZ * DIN * NCH * NST];  // per-chunk decay products
__device__ float g_hloc [(size_t)BSZ * DIN * NCH * NST];  // per-chunk local final states
__device__ float g_H0   [(size_t)BSZ * DIN * NCH * NST];  // per-chunk initial states

// ---------------------------------------------------------------------------
// LayerNorm: one block per (b,l) row of 1024
// ---------------------------------------------------------------------------
__global__ void ln_kernel(const float* __restrict__ x,
                          const float* __restrict__ w,
                          const float* __restrict__ b)
{
    __shared__ float sh[8];
    int row = blockIdx.x;
    const float* xr = x + (size_t)row * DM;
    int i0 = threadIdx.x * 4;
    float4 v = *(const float4*)(xr + i0);

    int lane = threadIdx.x & 31, wid = threadIdx.x >> 5;

    float s = v.x + v.y + v.z + v.w;
    #pragma unroll
    for (int o = 16; o > 0; o >>= 1) s += __shfl_down_sync(0xffffffffu, s, o);
    if (lane == 0) sh[wid] = s;
    __syncthreads();
    float t = (threadIdx.x < 8) ? sh[threadIdx.x] : 0.f;
    if (wid == 0) {
        #pragma unroll
        for (int o = 4; o > 0; o >>= 1) t += __shfl_down_sync(0xffffffffu, t, o);
        if (lane == 0) sh[0] = t;
    }
    __syncthreads();
    float mu = sh[0] * (1.f / DM);
    __syncthreads();

    float d0 = v.x - mu, d1 = v.y - mu, d2 = v.z - mu, d3 = v.w - mu;
    float ss = d0*d0 + d1*d1 + d2*d2 + d3*d3;
    #pragma unroll
    for (int o = 16; o > 0; o >>= 1) ss += __shfl_down_sync(0xffffffffu, ss, o);
    if (lane == 0) sh[wid] = ss;
    __syncthreads();
    t = (threadIdx.x < 8) ? sh[threadIdx.x] : 0.f;
    if (wid == 0) {
        #pragma unroll
        for (int o = 4; o > 0; o >>= 1) t += __shfl_down_sync(0xffffffffu, t, o);
        if (lane == 0) sh[0] = t;
    }
    __syncthreads();
    float rstd = rsqrtf(sh[0] * (1.f / DM) + 1e-5f);

    float4 wv = *(const float4*)(w + i0);
    float4 bv = *(const float4*)(b + i0);
    float4 o4;
    o4.x = d0 * rstd * wv.x + bv.x;
    o4.y = d1 * rstd * wv.y + bv.y;
    o4.z = d2 * rstd * wv.z + bv.z;
    o4.w = d3 * rstd * wv.w + bv.w;
    *(float4*)(g_xn + (size_t)row * DM + i0) = o4;
}

// ---------------------------------------------------------------------------
// Generic fp32 SGEMM, C[M,N] = A[M,K] * B[K,N] (+ epilogue)
// EPI: 0 = none, 1 = +bias then softplus (delta), 2 = +residual (final out)
// ASEL/CSEL select the device-global scratch buffers in-kernel (no symbol API)
// ---------------------------------------------------------------------------
__device__ __forceinline__ float softplusf(float v)
{
    return v > 20.f ? v : log1pf(expf(v));
}

template<int M, int N, int K, int EPI, int ASEL, int CSEL>
__global__ __launch_bounds__(256, 2)
void sgemm_kernel(const float* __restrict__ B,
                  const float* __restrict__ bias,
                  const float* __restrict__ resid,
                  float* __restrict__ Cext)
{
    const float* A = (ASEL == 0) ? g_xn : (ASEL == 1) ? g_u : g_gate;
    float* C = (CSEL == 0) ? g_xz : (CSEL == 1) ? g_delta : Cext;

    constexpr int BM = 128, BN = 128, BK = 16;
    __shared__ float As[BK][BM + 4];
    __shared__ float Bs[BK][BN];

    int tid = threadIdx.x;
    int bm = blockIdx.y * BM, bn = blockIdx.x * BN;
    int a_m = tid >> 2;            // 0..63
    int a_k = (tid & 3) << 2;      // 0,4,8,12
    int b_k = tid >> 5;            // 0..7
    int b_n = (tid & 31) << 2;     // 0..124
    int tx = tid & 15, ty = tid >> 4;

    float acc[8][8];
    #pragma unroll
    for (int i = 0; i < 8; i++)
        #pragma unroll
        for (int j = 0; j < 8; j++) acc[i][j] = 0.f;

    for (int k0 = 0; k0 < K; k0 += BK) {
        #pragma unroll
        for (int r = 0; r < 2; r++) {
            float4 v = *(const float4*)(A + (size_t)(bm + a_m + r * 64) * K + k0 + a_k);
            As[a_k + 0][a_m + r * 64] = v.x;
            As[a_k + 1][a_m + r * 64] = v.y;
            As[a_k + 2][a_m + r * 64] = v.z;
            As[a_k + 3][a_m + r * 64] = v.w;
        }
        #pragma unroll
        for (int r = 0; r < 2; r++) {
            *(float4*)(&Bs[b_k + r * 8][b_n]) =
                *(const float4*)(B + (size_t)(k0 + b_k + r * 8) * N + bn + b_n);
        }
        __syncthreads();

        #pragma unroll
        for (int kk = 0; kk < BK; kk++) {
            float a[8], bb[8];
            *(float4*)(a)      = *(const float4*)(&As[kk][ty * 8]);
            *(float4*)(a + 4)  = *(const float4*)(&As[kk][ty * 8 + 4]);
            *(float4*)(bb)     = *(const float4*)(&Bs[kk][tx * 8]);
            *(float4*)(bb + 4) = *(const float4*)(&Bs[kk][tx * 8 + 4]);
            #pragma unroll
            for (int i = 0; i < 8; i++)
                #pragma unroll
                for (int j = 0; j < 8; j++)
                    acc[i][j] = fmaf(a[i], bb[j], acc[i][j]);
        }
        __syncthreads();
    }

    #pragma unroll
    for (int i = 0; i < 8; i++) {
        size_t row = (size_t)(bm + ty * 8 + i);
        #pragma unroll
        for (int j = 0; j < 8; j += 4) {
            int col = bn + tx * 8 + j;
            float4 v;
            v.x = acc[i][j]; v.y = acc[i][j + 1]; v.z = acc[i][j + 2]; v.w = acc[i][j + 3];
            if constexpr (EPI == 1) {
                v.x = softplusf(v.x + bias[col]);
                v.y = softplusf(v.y + bias[col + 1]);
                v.z = softplusf(v.z + bias[col + 2]);
                v.w = softplusf(v.w + bias[col + 3]);
            } else if constexpr (EPI == 2) {
                float4 r4 = *(const float4*)(resid + row * N + col);
                v.x += r4.x; v.y += r4.y; v.z += r4.z; v.w += r4.w;
            }
            *(float4*)(C + row * N + col) = v;
        }
    }
}

// ---------------------------------------------------------------------------
// Depthwise causal conv1d (taps=4, left pad 3) + bias + SiLU.
// x_path lives in g_xz[..., 0:DIN]; output -> g_u
// ---------------------------------------------------------------------------
__global__ void conv_silu_kernel(const float* __restrict__ wconv,
                                 const float* __restrict__ bconv)
{
    size_t idx = (size_t)blockIdx.x * blockDim.x + threadIdx.x;
    if (idx >= (size_t)ROWS * DIN) return;
    int d = (int)(idx & (DIN - 1));
    size_t row = idx >> 11;          // b*L + l
    int l = (int)(row & (L - 1));

    float w0 = wconv[d * 4 + 0], w1 = wconv[d * 4 + 1];
    float w2 = wconv[d * 4 + 2], w3 = wconv[d * 4 + 3];
    const float* base = g_xz + row * (size_t)(2 * DIN) + d;

    float s = bconv[d];
    s = fmaf(base[0], w3, s);                                  // tap j=3 -> offset 0
    if (l >= 1) s = fmaf(*(base - 1 * 2 * DIN), w2, s);
    if (l >= 2) s = fmaf(*(base - 2 * 2 * DIN), w1, s);
    if (l >= 3) s = fmaf(*(base - 3 * 2 * DIN), w0, s);

    float sig = 1.f / (1.f + __expf(-s));
    g_u[idx] = s * sig;
}

// ---------------------------------------------------------------------------
// Bseq / Cseq: tall-skinny GEMM, one block per (b,l) row, K=2048, N=16+16
// ---------------------------------------------------------------------------
__global__ void bc_kernel(const float* __restrict__ wb,
                          const float* __restrict__ wc)
{
    __shared__ float sh[8][32];
    int row = blockIdx.x;
    const float* ur = g_u + (size_t)row * DIN;

    float aB[16], aC[16];
    #pragma unroll
    for (int n = 0; n < 16; n++) { aB[n] = 0.f; aC[n] = 0.f; }

    for (int k = threadIdx.x; k < DIN; k += 256) {
        float uv = ur[k];
        const float4* pb = (const float4*)(wb + (size_t)k * NST);
        const float4* pc = (const float4*)(wc + (size_t)k * NST);
        #pragma unroll
        for (int q = 0; q < 4; q++) {
            float4 b4 = pb[q], c4 = pc[q];
            aB[4*q+0] = fmaf(uv, b4.x, aB[4*q+0]);
            aB[4*q+1] = fmaf(uv, b4.y, aB[4*q+1]);
            aB[4*q+2] = fmaf(uv, b4.z, aB[4*q+2]);
            aB[4*q+3] = fmaf(uv, b4.w, aB[4*q+3]);
            aC[4*q+0] = fmaf(uv, c4.x, aC[4*q+0]);
            aC[4*q+1] = fmaf(uv, c4.y, aC[4*q+1]);
            aC[4*q+2] = fmaf(uv, c4.z, aC[4*q+2]);
            aC[4*q+3] = fmaf(uv, c4.w, aC[4*q+3]);
        }
    }

    int lane = threadIdx.x & 31, wid = threadIdx.x >> 5;
    #pragma unroll
    for (int n = 0; n < 16; n++) {
        #pragma unroll
        for (int o = 16; o > 0; o >>= 1) {
            aB[n] += __shfl_down_sync(0xffffffffu, aB[n], o);
            aC[n] += __shfl_down_sync(0xffffffffu, aC[n], o);
        }
    }
    if (lane == 0) {
        #pragma unroll
        for (int n = 0; n < 16; n++) { sh[wid][n] = aB[n]; sh[wid][16 + n] = aC[n]; }
    }
    __syncthreads();
    if (threadIdx.x < 32) {
        float s = 0.f;
        #pragma unroll
        for (int w = 0; w < 8; w++) s += sh[w][threadIdx.x];
        if (threadIdx.x < 16)
            g_Bseq[(size_t)row * NST + threadIdx.x] = s;
        else
            g_Cseq[(size_t)row * NST + threadIdx.x - 16] = s;
    }
}

// ---------------------------------------------------------------------------
// Chunked selective scan.
// Pass 1 (PASS2=false): per (b,d,chunk) compute decay product P and local
//   final state with h0=0. Pass 2 (PASS2=true): replay with correct H0,
//   emit gate = y * silu(z).
// exp(delta*A[n]): runtime structure check A[n] == (n+1)*A[0] -> one exp +
//   power tree; general fallback: 16 exps. Both bit-level safe for 1e-3 tol.
// ---------------------------------------------------------------------------
template<bool PASS2>
__global__ void scan_kernel(const float* __restrict__ A_log,
                            const float* __restrict__ D_param)
{
    int gid = blockIdx.x * blockDim.x + threadIdx.x;
    if (gid >= BSZ * DIN * NCH) return;
    int d = gid & (DIN - 1);
    int c = (gid >> 11) & (NCH - 1);
    int b = gid >> 15;

    float A[NST];
    #pragma unroll
    for (int n = 0; n < NST; n++) A[n] = -__expf(A_log[d * NST + n]);

    bool structured = true;
    #pragma unroll
    for (int n = 1; n < NST; n++) {
        float t = (float)(n + 1) * A[0];
        if (fabsf(A[n] - t) > 1e-4f * fabsf(t)) structured = false;
    }

    float h[NST], P[NST];
    #pragma unroll
    for (int n = 0; n < NST; n++) { h[n] = 0.f; P[n] = 1.f; }

    size_t sidx = ((size_t)((b * DIN + d) * NCH + c)) * NST;
    if constexpr (PASS2) {
        #pragma unroll
        for (int n = 0; n < NST; n += 4) {
            float4 v = *(const float4*)(g_H0 + sidx + n);
            h[n] = v.x; h[n+1] = v.y; h[n+2] = v.z; h[n+3] = v.w;
        }
    }
    float Dp = PASS2 ? D_param[d] : 0.f;

    size_t row0 = (size_t)b * L + (size_t)c * LC;
    for (int t = 0; t < LC; t++) {
        size_t row = row0 + t;
        float dl = g_delta[row * DIN + d];
        float uv = g_u[row * DIN + d];
        float du = dl * uv;

        float Bv[NST];
        #pragma unroll
        for (int n = 0; n < NST; n += 4) {
            float4 v = *(const float4*)(g_Bseq + row * NST + n);
            Bv[n] = v.x; Bv[n+1] = v.y; Bv[n+2] = v.z; Bv[n+3] = v.w;
        }

        float e[NST];
        if (structured) {
            float e1 = __expf(dl * A[0]);
            float e2 = e1 * e1, e4 = e2 * e2, e8 = e4 * e4;
            e[0]  = e1;           e[1]  = e2;           e[2]  = e2 * e1;
            e[3]  = e4;           e[4]  = e4 * e1;      e[5]  = e4 * e2;
            e[6]  = e4 * e2 * e1; e[7]  = e8;           e[8]  = e8 * e1;
            e[9]  = e8 * e2;      e[10] = e8 * e2 * e1; e[11] = e8 * e4;
            e[12] = e8 * e4 * e1; e[13] = e8 * e4 * e2; e[14] = e8 * e4 * e2 * e1;
            e[15] = e8 * e8;
        } else {
            #pragma unroll
            for (int n = 0; n < NST; n++) e[n] = __expf(dl * A[n]);
        }

        #pragma unroll
        for (int n = 0; n < NST; n++) {
            h[n] = fmaf(e[n], h[n], du * Bv[n]);
            if constexpr (!PASS2) P[n] *= e[n];
        }

        if constexpr (PASS2) {
            float Cv[NST];
            #pragma unroll
            for (int n = 0; n < NST; n += 4) {
                float4 v = *(const float4*)(g_Cseq + row * NST + n);
                Cv[n] = v.x; Cv[n+1] = v.y; Cv[n+2] = v.z; Cv[n+3] = v.w;
            }
            float y = Dp * uv;
            #pragma unroll
            for (int n = 0; n < NST; n++) y = fmaf(h[n], Cv[n], y);

            float z = g_xz[row * (size_t)(2 * DIN) + DIN + d];
            float sz = z / (1.f + __expf(-z));
            g_gate[row * DIN + d] = y * sz;
        }
    }

    if constexpr (!PASS2) {
        #pragma unroll
        for (int n = 0; n < NST; n += 4) {
            float4 vp = { P[n], P[n+1], P[n+2], P[n+3] };
            float4 vh = { h[n], h[n+1], h[n+2], h[n+3] };
            *(float4*)(g_P + sidx + n)    = vp;
            *(float4*)(g_hloc + sidx + n) = vh;
        }
    }
}

// Sequential combine over the 16 chunks (cheap): H0[c+1] = P[c]*H0[c] + hloc[c]
__global__ void scan_combine_kernel()
{
    int gid = blockIdx.x * blockDim.x + threadIdx.x;
    if (gid >= BSZ * DIN) return;
    size_t base = (size_t)gid * NCH * NST;
    float H[NST];
    #pragma unroll
    for (int n = 0; n < NST; n++) H[n] = 0.f;
    for (int c = 0; c < NCH; c++) {
        size_t idx = base + (size_t)c * NST;
        #pragma unroll
        for (int n = 0; n < NST; n += 4) {
            float4 v = { H[n], H[n+1], H[n+2], H[n+3] };
            *(float4*)(g_H0 + idx + n) = v;
        }
        #pragma unroll
        for (int n = 0; n < NST; n++)
            H[n] = fmaf(g_P[idx + n], H[n], g_hloc[idx + n]);
    }
}

// ---------------------------------------------------------------------------
// Launch
// ---------------------------------------------------------------------------
extern "C" void kernel_launch(void* const* d_in, const int* in_sizes, int n_in,
                              void* d_out, int out_size)
{
    const float* x       = (const float*)d_in[0];
    const float* w_norm  = (const float*)d_in[1];
    const float* b_norm  = (const float*)d_in[2];
    const float* w_in    = (const float*)d_in[3];
    const float* w_conv  = (const float*)d_in[4];
    const float* b_conv  = (const float*)d_in[5];
    const float* A_log   = (const float*)d_in[6];
    const float* w_b     = (const float*)d_in[7];
    const float* w_c     = (const float*)d_in[8];
    const float* w_delta = (const float*)d_in[9];
    const float* b_delta = (const float*)d_in[10];
    const float* D_param = (const float*)d_in[11];
    const float* w_out   = (const float*)d_in[12];
    float* out = (float*)d_out;

    // 1. LayerNorm
    ln_kernel<<<ROWS, 256>>>(x, w_norm, b_norm);

    // 2. xz = xn @ w_in   (4096 x 4096, K=1024)
    sgemm_kernel<ROWS, 2 * DIN, DM, 0, 0, 0>
        <<<dim3((2 * DIN) / 128, ROWS / 128), 256>>>(w_in, nullptr, nullptr, nullptr);

    // 3. depthwise causal conv + bias + silu -> u
    conv_silu_kernel<<<(int)(((size_t)ROWS * DIN + 255) / 256), 256>>>(w_conv, b_conv);

    // 4a. Bseq/Cseq = u @ w_b, u @ w_c
    bc_kernel<<<ROWS, 256>>>(w_b, w_c);

    // 4b. delta = softplus(u @ w_delta + b_delta)   (4096 x 2048, K=2048)
    sgemm_kernel<ROWS, DIN, DIN, 1, 1, 1>
        <<<dim3(DIN / 128, ROWS / 128), 256>>>(w_delta, b_delta, nullptr, nullptr);

    // 5. chunked selective scan (pass1 -> combine -> pass2 emits gate)
    scan_kernel<false><<<(BSZ * DIN * NCH) / 256, 256>>>(A_log, D_param);
    scan_combine_kernel<<<(BSZ * DIN) / 256, 256>>>();
    scan_kernel<true><<<(BSZ * DIN * NCH) / 256, 256>>>(A_log, D_param);

    // 6. out = gate @ w_out + residual   (4096 x 1024, K=2048)
    sgemm_kernel<ROWS, DM, DIN, 2, 2, 2>
        <<<dim3(DM / 128, ROWS / 128), 256>>>(w_out, nullptr, x, out);
}

// round 2
// speedup vs baseline: 1.0006x; 1.0006x over previous
#include <cuda_runtime.h>

// ---------------------------------------------------------------------------
// Problem constants (fixed by the dataset)
// ---------------------------------------------------------------------------
constexpr int BSZ = 2;
constexpr int L   = 2048;
constexpr int DM  = 1024;        // d_model
constexpr int DIN = 2048;        // d_inner
constexpr int NST = 16;          // d_state
constexpr int ROWS = BSZ * L;    // 4096 flattened (b,l) rows
constexpr int NCH  = 16;         // scan chunks
constexpr int LC   = L / NCH;    // 128 steps per chunk

// ---------------------------------------------------------------------------
// Scratch (static device globals -- no runtime allocation allowed)
// ---------------------------------------------------------------------------
__device__ float g_xn   [(size_t)ROWS * DM];        // layernorm output
__device__ float g_xz   [(size_t)ROWS * 2 * DIN];   // in-proj output (x_path | z_path)
__device__ float g_u    [(size_t)ROWS * DIN];       // conv + silu output
__device__ float g_delta[(size_t)ROWS * DIN];       // softplus(u@w_delta + b_delta)
__device__ float g_Bseq [(size_t)ROWS * NST];
__device__ float g_Cseq [(size_t)ROWS * NST];
__device__ float g_gate [(size_t)ROWS * DIN];       // y * silu(z)
__device__ float g_P    [(size_t)BSZ * DIN * NCH * NST];  // per-chunk decay products
__device__ float g_hloc [(size_t)BSZ * DIN * NCH * NST];  // per-chunk local final states
__device__ float g_H0   [(size_t)BSZ * DIN * NCH * NST];  // per-chunk initial states

// ---------------------------------------------------------------------------
// LayerNorm: one block per (b,l) row of 1024
// ---------------------------------------------------------------------------
__global__ void ln_kernel(const float* __restrict__ x,
                          const float* __restrict__ w,
                          const float* __restrict__ b)
{
    __shared__ float sh[8];
    int row = blockIdx.x;
    const float* xr = x + (size_t)row * DM;
    int i0 = threadIdx.x * 4;
    float4 v = *(const float4*)(xr + i0);

    int lane = threadIdx.x & 31, wid = threadIdx.x >> 5;

    float s = v.x + v.y + v.z + v.w;
    #pragma unroll
    for (int o = 16; o > 0; o >>= 1) s += __shfl_down_sync(0xffffffffu, s, o);
    if (lane == 0) sh[wid] = s;
    __syncthreads();
    float t = (threadIdx.x < 8) ? sh[threadIdx.x] : 0.f;
    if (wid == 0) {
        #pragma unroll
        for (int o = 4; o > 0; o >>= 1) t += __shfl_down_sync(0xffffffffu, t, o);
        if (lane == 0) sh[0] = t;
    }
    __syncthreads();
    float mu = sh[0] * (1.f / DM);
    __syncthreads();

    float d0 = v.x - mu, d1 = v.y - mu, d2 = v.z - mu, d3 = v.w - mu;
    float ss = d0*d0 + d1*d1 + d2*d2 + d3*d3;
    #pragma unroll
    for (int o = 16; o > 0; o >>= 1) ss += __shfl_down_sync(0xffffffffu, ss, o);
    if (lane == 0) sh[wid] = ss;
    __syncthreads();
    t = (threadIdx.x < 8) ? sh[threadIdx.x] : 0.f;
    if (wid == 0) {
        #pragma unroll
        for (int o = 4; o > 0; o >>= 1) t += __shfl_down_sync(0xffffffffu, t, o);
        if (lane == 0) sh[0] = t;
    }
    __syncthreads();
    float rstd = rsqrtf(sh[0] * (1.f / DM) + 1e-5f);

    float4 wv = *(const float4*)(w + i0);
    float4 bv = *(const float4*)(b + i0);
    float4 o4;
    o4.x = d0 * rstd * wv.x + bv.x;
    o4.y = d1 * rstd * wv.y + bv.y;
    o4.z = d2 * rstd * wv.z + bv.z;
    o4.w = d3 * rstd * wv.w + bv.w;
    *(float4*)(g_xn + (size_t)row * DM + i0) = o4;
}

// ---------------------------------------------------------------------------
// Generic fp32 SGEMM, C[M,N] = A[M,K] * B[K,N] (+ epilogue)
// EPI: 0 = none, 1 = +bias then softplus (delta), 2 = +residual (final out)
// ASEL/CSEL select the device-global scratch buffers in-kernel (no symbol API)
// ---------------------------------------------------------------------------
__device__ __forceinline__ float softplusf(float v)
{
    return v > 20.f ? v : log1pf(expf(v));
}

template<int M, int N, int K, int EPI, int ASEL, int CSEL>
__global__ __launch_bounds__(256, 2)
void sgemm_kernel(const float* __restrict__ B,
                  const float* __restrict__ bias,
                  const float* __restrict__ resid,
                  float* __restrict__ Cext)
{
    const float* A = (ASEL == 0) ? g_xn : (ASEL == 1) ? g_u : g_gate;
    float* C = (CSEL == 0) ? g_xz : (CSEL == 1) ? g_delta : Cext;

    constexpr int BM = 128, BN = 128, BK = 16;
    __shared__ float As[BK][BM + 4];
    __shared__ float Bs[BK][BN];

    int tid = threadIdx.x;
    int bm = blockIdx.y * BM, bn = blockIdx.x * BN;
    int a_m = tid >> 2;            // 0..63
    int a_k = (tid & 3) << 2;      // 0,4,8,12
    int b_k = tid >> 5;            // 0..7
    int b_n = (tid & 31) << 2;     // 0..124
    int tx = tid & 15, ty = tid >> 4;

    float acc[8][8];
    #pragma unroll
    for (int i = 0; i < 8; i++)
        #pragma unroll
        for (int j = 0; j < 8; j++) acc[i][j] = 0.f;

    for (int k0 = 0; k0 < K; k0 += BK) {
        #pragma unroll
        for (int r = 0; r < 2; r++) {
            float4 v = *(const float4*)(A + (size_t)(bm + a_m + r * 64) * K + k0 + a_k);
            As[a_k + 0][a_m + r * 64] = v.x;
            As[a_k + 1][a_m + r * 64] = v.y;
            As[a_k + 2][a_m + r * 64] = v.z;
            As[a_k + 3][a_m + r * 64] = v.w;
        }
        #pragma unroll
        for (int r = 0; r < 2; r++) {
            *(float4*)(&Bs[b_k + r * 8][b_n]) =
                *(const float4*)(B + (size_t)(k0 + b_k + r * 8) * N + bn + b_n);
        }
        __syncthreads();

        #pragma unroll
        for (int kk = 0; kk < BK; kk++) {
            float a[8], bb[8];
            *(float4*)(a)      = *(const float4*)(&As[kk][ty * 8]);
            *(float4*)(a + 4)  = *(const float4*)(&As[kk][ty * 8 + 4]);
            *(float4*)(bb)     = *(const float4*)(&Bs[kk][tx * 8]);
            *(float4*)(bb + 4) = *(const float4*)(&Bs[kk][tx * 8 + 4]);
            #pragma unroll
            for (int i = 0; i < 8; i++)
                #pragma unroll
                for (int j = 0; j < 8; j++)
                    acc[i][j] = fmaf(a[i], bb[j], acc[i][j]);
        }
        __syncthreads();
    }

    #pragma unroll
    for (int i = 0; i < 8; i++) {
        size_t row = (size_t)(bm + ty * 8 + i);
        #pragma unroll
        for (int j = 0; j < 8; j += 4) {
            int col = bn + tx * 8 + j;
            float4 v;
            v.x = acc[i][j]; v.y = acc[i][j + 1]; v.z = acc[i][j + 2]; v.w = acc[i][j + 3];
            if constexpr (EPI == 1) {
                v.x = softplusf(v.x + bias[col]);
                v.y = softplusf(v.y + bias[col + 1]);
                v.z = softplusf(v.z + bias[col + 2]);
                v.w = softplusf(v.w + bias[col + 3]);
            } else if constexpr (EPI == 2) {
                float4 r4 = *(const float4*)(resid + row * N + col);
                v.x += r4.x; v.y += r4.y; v.z += r4.z; v.w += r4.w;
            }
            *(float4*)(C + row * N + col) = v;
        }
    }
}

// ---------------------------------------------------------------------------
// Depthwise causal conv1d (taps=4, left pad 3) + bias + SiLU.
// x_path lives in g_xz[..., 0:DIN]; output -> g_u
// ---------------------------------------------------------------------------
__global__ void conv_silu_kernel(const float* __restrict__ wconv,
                                 const float* __restrict__ bconv)
{
    size_t idx = (size_t)blockIdx.x * blockDim.x + threadIdx.x;
    if (idx >= (size_t)ROWS * DIN) return;
    int d = (int)(idx & (DIN - 1));
    size_t row = idx >> 11;          // b*L + l
    int l = (int)(row & (L - 1));

    float w0 = wconv[d * 4 + 0], w1 = wconv[d * 4 + 1];
    float w2 = wconv[d * 4 + 2], w3 = wconv[d * 4 + 3];
    const float* base = g_xz + row * (size_t)(2 * DIN) + d;

    float s = bconv[d];
    s = fmaf(base[0], w3, s);                                  // tap j=3 -> offset 0
    if (l >= 1) s = fmaf(*(base - 1 * 2 * DIN), w2, s);
    if (l >= 2) s = fmaf(*(base - 2 * 2 * DIN), w1, s);
    if (l >= 3) s = fmaf(*(base - 3 * 2 * DIN), w0, s);

    float sig = 1.f / (1.f + __expf(-s));
    g_u[idx] = s * sig;
}

// ---------------------------------------------------------------------------
// Bseq / Cseq: tall-skinny GEMM, one block per (b,l) row, K=2048, N=16+16
// ---------------------------------------------------------------------------
__global__ void bc_kernel(const float* __restrict__ wb,
                          const float* __restrict__ wc)
{
    __shared__ float sh[8][32];
    int row = blockIdx.x;
    const float* ur = g_u + (size_t)row * DIN;

    float aB[16], aC[16];
    #pragma unroll
    for (int n = 0; n < 16; n++) { aB[n] = 0.f; aC[n] = 0.f; }

    for (int k = threadIdx.x; k < DIN; k += 256) {
        float uv = ur[k];
        const float4* pb = (const float4*)(wb + (size_t)k * NST);
        const float4* pc = (const float4*)(wc + (size_t)k * NST);
        #pragma unroll
        for (int q = 0; q < 4; q++) {
            float4 b4 = pb[q], c4 = pc[q];
            aB[4*q+0] = fmaf(uv, b4.x, aB[4*q+0]);
            aB[4*q+1] = fmaf(uv, b4.y, aB[4*q+1]);
            aB[4*q+2] = fmaf(uv, b4.z, aB[4*q+2]);
            aB[4*q+3] = fmaf(uv, b4.w, aB[4*q+3]);
            aC[4*q+0] = fmaf(uv, c4.x, aC[4*q+0]);
            aC[4*q+1] = fmaf(uv, c4.y, aC[4*q+1]);
            aC[4*q+2] = fmaf(uv, c4.z, aC[4*q+2]);
            aC[4*q+3] = fmaf(uv, c4.w, aC[4*q+3]);
        }
    }

    int lane = threadIdx.x & 31, wid = threadIdx.x >> 5;
    #pragma unroll
    for (int n = 0; n < 16; n++) {
        #pragma unroll
        for (int o = 16; o > 0; o >>= 1) {
            aB[n] += __shfl_down_sync(0xffffffffu, aB[n], o);
            aC[n] += __shfl_down_sync(0xffffffffu, aC[n], o);
        }
    }
    if (lane == 0) {
        #pragma unroll
        for (int n = 0; n < 16; n++) { sh[wid][n] = aB[n]; sh[wid][16 + n] = aC[n]; }
    }
    __syncthreads();
    if (threadIdx.x < 32) {
        float s = 0.f;
        #pragma unroll
        for (int w = 0; w < 8; w++) s += sh[w][threadIdx.x];
        if (threadIdx.x < 16)
            g_Bseq[(size_t)row * NST + threadIdx.x] = s;
        else
            g_Cseq[(size_t)row * NST + threadIdx.x - 16] = s;
    }
}

// ---------------------------------------------------------------------------
// Chunked selective scan.
// Pass 1 (PASS2=false): per (b,d,chunk) compute decay product P and local
//   final state with h0=0. Pass 2 (PASS2=true): replay with correct H0,
//   emit gate = y * silu(z).
// exp(delta*A[n]): runtime structure check A[n] == (n+1)*A[0] -> one exp +
//   power tree; general fallback: 16 exps. Both bit-level safe for 1e-3 tol.
// ---------------------------------------------------------------------------
template<bool PASS2>
__global__ void scan_kernel(const float* __restrict__ A_log,
                            const float* __restrict__ D_param)
{
    int gid = blockIdx.x * blockDim.x + threadIdx.x;
    if (gid >= BSZ * DIN * NCH) return;
    int d = gid & (DIN - 1);
    int c = (gid >> 11) & (NCH - 1);
    int b = gid >> 15;

    float A[NST];
    #pragma unroll
    for (int n = 0; n < NST; n++) A[n] = -__expf(A_log[d * NST + n]);

    bool structured = true;
    #pragma unroll
    for (int n = 1; n < NST; n++) {
        float t = (float)(n + 1) * A[0];
        if (fabsf(A[n] - t) > 1e-4f * fabsf(t)) structured = false;
    }

    float h[NST], P[NST];
    #pragma unroll
    for (int n = 0; n < NST; n++) { h[n] = 0.f; P[n] = 1.f; }

    size_t sidx = ((size_t)((b * DIN + d) * NCH + c)) * NST;
    if constexpr (PASS2) {
        #pragma unroll
        for (int n = 0; n < NST; n += 4) {
            float4 v = *(const float4*)(g_H0 + sidx + n);
            h[n] = v.x; h[n+1] = v.y; h[n+2] = v.z; h[n+3] = v.w;
        }
    }
    float Dp = PASS2 ? D_param[d] : 0.f;

    size_t row0 = (size_t)b * L + (size_t)c * LC;
    for (int t = 0; t < LC; t++) {
        size_t row = row0 + t;
        float dl = g_delta[row * DIN + d];
        float uv = g_u[row * DIN + d];
        float du = dl * uv;

        float Bv[NST];
        #pragma unroll
        for (int n = 0; n < NST; n += 4) {
            float4 v = *(const float4*)(g_Bseq + row * NST + n);
            Bv[n] = v.x; Bv[n+1] = v.y; Bv[n+2] = v.z; Bv[n+3] = v.w;
        }

        float e[NST];
        if (structured) {
            float e1 = __expf(dl * A[0]);
            float e2 = e1 * e1, e4 = e2 * e2, e8 = e4 * e4;
            e[0]  = e1;           e[1]  = e2;           e[2]  = e2 * e1;
            e[3]  = e4;           e[4]  = e4 * e1;      e[5]  = e4 * e2;
            e[6]  = e4 * e2 * e1; e[7]  = e8;           e[8]  = e8 * e1;
            e[9]  = e8 * e2;      e[10] = e8 * e2 * e1; e[11] = e8 * e4;
            e[12] = e8 * e4 * e1; e[13] = e8 * e4 * e2; e[14] = e8 * e4 * e2 * e1;
            e[15] = e8 * e8;
        } else {
            #pragma unroll
            for (int n = 0; n < NST; n++) e[n] = __expf(dl * A[n]);
        }

        #pragma unroll
        for (int n = 0; n < NST; n++) {
            h[n] = fmaf(e[n], h[n], du * Bv[n]);
            if constexpr (!PASS2) P[n] *= e[n];
        }

        if constexpr (PASS2) {
            float Cv[NST];
            #pragma unroll
            for (int n = 0; n < NST; n += 4) {
                float4 v = *(const float4*)(g_Cseq + row * NST + n);
                Cv[n] = v.x; Cv[n+1] = v.y; Cv[n+2] = v.z; Cv[n+3] = v.w;
            }
            float y = Dp * uv;
            #pragma unroll
            for (int n = 0; n < NST; n++) y = fmaf(h[n], Cv[n], y);

            float z = g_xz[row * (size_t)(2 * DIN) + DIN + d];
            float sz = z / (1.f + __expf(-z));
            g_gate[row * DIN + d] = y * sz;
        }
    }

    if constexpr (!PASS2) {
        #pragma unroll
        for (int n = 0; n < NST; n += 4) {
            float4 vp = { P[n], P[n+1], P[n+2], P[n+3] };
            float4 vh = { h[n], h[n+1], h[n+2], h[n+3] };
            *(float4*)(g_P + sidx + n)    = vp;
            *(float4*)(g_hloc + sidx + n) = vh;
        }
    }
}

// Sequential combine over the 16 chunks (cheap): H0[c+1] = P[c]*H0[c] + hloc[c]
__global__ void scan_combine_kernel()
{
    int gid = blockIdx.x * blockDim.x + threadIdx.x;
    if (gid >= BSZ * DIN) return;
    size_t base = (size_t)gid * NCH * NST;
    float H[NST];
    #pragma unroll
    for (int n = 0; n < NST; n++) H[n] = 0.f;
    for (int c = 0; c < NCH; c++) {
        size_t idx = base + (size_t)c * NST;
        #pragma unroll
        for (int n = 0; n < NST; n += 4) {
            float4 v = { H[n], H[n+1], H[n+2], H[n+3] };
            *(float4*)(g_H0 + idx + n) = v;
        }
        #pragma unroll
        for (int n = 0; n < NST; n++)
            H[n] = fmaf(g_P[idx + n], H[n], g_hloc[idx + n]);
    }
}

// ---------------------------------------------------------------------------
// Launch
// ---------------------------------------------------------------------------
extern "C" void kernel_launch(void* const* d_in, const int* in_sizes, int n_in,
                              void* d_out, int out_size)
{
    const float* x       = (const float*)d_in[0];
    const float* w_norm  = (const float*)d_in[1];
    const float* b_norm  = (const float*)d_in[2];
    const float* w_in    = (const float*)d_in[3];
    const float* w_conv  = (const float*)d_in[4];
    const float* b_conv  = (const float*)d_in[5];
    const float* A_log   = (const float*)d_in[6];
    const float* w_b     = (const float*)d_in[7];
    const float* w_c     = (const float*)d_in[8];
    const float* w_delta = (const float*)d_in[9];
    const float* b_delta = (const float*)d_in[10];
    const float* D_param = (const float*)d_in[11];
    const float* w_out   = (const float*)d_in[12];
    float* out = (float*)d_out;

    // 1. LayerNorm
    ln_kernel<<<ROWS, 256>>>(x, w_norm, b_norm);

    // 2. xz = xn @ w_in   (4096 x 4096, K=1024)
    sgemm_kernel<ROWS, 2 * DIN, DM, 0, 0, 0>
        <<<dim3((2 * DIN) / 128, ROWS / 128), 256>>>(w_in, nullptr, nullptr, nullptr);

    // 3. depthwise causal conv + bias + silu -> u
    conv_silu_kernel<<<(int)(((size_t)ROWS * DIN + 255) / 256), 256>>>(w_conv, b_conv);

    // 4a. Bseq/Cseq = u @ w_b, u @ w_c
    bc_kernel<<<ROWS, 256>>>(w_b, w_c);

    // 4b. delta = softplus(u @ w_delta + b_delta)   (4096 x 2048, K=2048)
    sgemm_kernel<ROWS, DIN, DIN, 1, 1, 1>
        <<<dim3(DIN / 128, ROWS / 128), 256>>>(w_delta, b_delta, nullptr, nullptr);

    // 5. chunked selective scan (pass1 -> combine -> pass2 emits gate)
    scan_kernel<false><<<(BSZ * DIN * NCH) / 256, 256>>>(A_log, D_param);
    scan_combine_kernel<<<(BSZ * DIN) / 256, 256>>>();
    scan_kernel<true><<<(BSZ * DIN * NCH) / 256, 256>>>(A_log, D_param);

    // 6. out = gate @ w_out + residual   (4096 x 1024, K=2048)
    sgemm_kernel<ROWS, DM, DIN, 2, 2, 2>
        <<<dim3(DM / 128, ROWS / 128), 256>>>(w_out, nullptr, x, out);
}

// round 3
// speedup vs baseline: 2.0499x; 2.0486x over previous
#include <cuda_runtime.h>
#include <cstdint>

// ---------------------------------------------------------------------------
// Problem constants (fixed by the dataset)
// ---------------------------------------------------------------------------
constexpr int BSZ = 2;
constexpr int L   = 2048;
constexpr int DM  = 1024;        // d_model
constexpr int DIN = 2048;        // d_inner
constexpr int NST = 16;          // d_state
constexpr int ROWS = BSZ * L;    // 4096 flattened (b,l) rows
constexpr int NCH  = 16;         // scan chunks
constexpr int LC   = L / NCH;    // 128 steps per chunk

// ---------------------------------------------------------------------------
// Scratch (static device globals -- no runtime allocation allowed)
// ---------------------------------------------------------------------------
__device__ float g_xn   [(size_t)ROWS * DM];        // layernorm output
__device__ float g_xz   [(size_t)ROWS * 2 * DIN];   // in-proj output (x_path | z_path)
__device__ float g_u    [(size_t)ROWS * DIN];       // conv + silu output
__device__ float g_delta[(size_t)ROWS * DIN];       // softplus(u@w_delta + b_delta)
__device__ float g_Bseq [(size_t)ROWS * NST];
__device__ float g_Cseq [(size_t)ROWS * NST];
__device__ float g_gate [(size_t)ROWS * DIN];       // y * silu(z)
__device__ float g_P    [(size_t)BSZ * DIN * NCH * NST];
__device__ float g_hloc [(size_t)BSZ * DIN * NCH * NST];
__device__ float g_H0   [(size_t)BSZ * DIN * NCH * NST];

// ---------------------------------------------------------------------------
// Helpers
// ---------------------------------------------------------------------------
__device__ __forceinline__ uint32_t f2tf32(float f)
{
    uint32_t r;
    asm("cvt.rna.tf32.f32 %0, %1;" : "=r"(r) : "f"(f));
    return r;
}

__device__ __forceinline__ float softplusf(float v)
{
    return v > 20.f ? v : log1pf(expf(v));
}

// ---------------------------------------------------------------------------
// LayerNorm: one block per (b,l) row of 1024
// ---------------------------------------------------------------------------
__global__ void ln_kernel(const float* __restrict__ x,
                          const float* __restrict__ w,
                          const float* __restrict__ b)
{
    __shared__ float sh[8];
    int row = blockIdx.x;
    const float* xr = x + (size_t)row * DM;
    int i0 = threadIdx.x * 4;
    float4 v = *(const float4*)(xr + i0);

    int lane = threadIdx.x & 31, wid = threadIdx.x >> 5;

    float s = v.x + v.y + v.z + v.w;
    #pragma unroll
    for (int o = 16; o > 0; o >>= 1) s += __shfl_down_sync(0xffffffffu, s, o);
    if (lane == 0) sh[wid] = s;
    __syncthreads();
    float t = (threadIdx.x < 8) ? sh[threadIdx.x] : 0.f;
    if (wid == 0) {
        #pragma unroll
        for (int o = 4; o > 0; o >>= 1) t += __shfl_down_sync(0xffffffffu, t, o);
        if (lane == 0) sh[0] = t;
    }
    __syncthreads();
    float mu = sh[0] * (1.f / DM);
    __syncthreads();

    float d0 = v.x - mu, d1 = v.y - mu, d2 = v.z - mu, d3 = v.w - mu;
    float ss = d0*d0 + d1*d1 + d2*d2 + d3*d3;
    #pragma unroll
    for (int o = 16; o > 0; o >>= 1) ss += __shfl_down_sync(0xffffffffu, ss, o);
    if (lane == 0) sh[wid] = ss;
    __syncthreads();
    t = (threadIdx.x < 8) ? sh[threadIdx.x] : 0.f;
    if (wid == 0) {
        #pragma unroll
        for (int o = 4; o > 0; o >>= 1) t += __shfl_down_sync(0xffffffffu, t, o);
        if (lane == 0) sh[0] = t;
    }
    __syncthreads();
    float rstd = rsqrtf(sh[0] * (1.f / DM) + 1e-5f);

    float4 wv = *(const float4*)(w + i0);
    float4 bv = *(const float4*)(b + i0);
    float4 o4;
    o4.x = d0 * rstd * wv.x + bv.x;
    o4.y = d1 * rstd * wv.y + bv.y;
    o4.z = d2 * rstd * wv.z + bv.z;
    o4.w = d3 * rstd * wv.w + bv.w;
    *(float4*)(g_xn + (size_t)row * DM + i0) = o4;
}

// ---------------------------------------------------------------------------
// TF32 tensor-core GEMM: C[M,N] = A[M,K] * B[K,N] (+ epilogue)
// mma.sync.m16n8k8.tf32, fp32 accumulate.
// BM=128, BN=128, BK=32, 256 threads (8 warps: 2 x-M, 4 x-N; warp tile 64x32)
// EPI: 0 = none, 1 = +bias then softplus, 2 = +residual
// ---------------------------------------------------------------------------
template<int M, int N, int K, int EPI, int ASEL, int CSEL>
__global__ __launch_bounds__(256, 2)
void tgemm_kernel(const float* __restrict__ Bmat,
                  const float* __restrict__ bias,
                  const float* __restrict__ resid,
                  float* __restrict__ Cext)
{
    const float* A = (ASEL == 0) ? g_xn : (ASEL == 1) ? g_u : g_gate;
    float* C = (CSEL == 0) ? g_xz : (CSEL == 1) ? g_delta : Cext;

    constexpr int BM = 128, BN = 128, BK = 32;
    constexpr int ASTR = BM + 8;   // stride -> conflict-free fragment loads
    constexpr int BSTR = BN + 8;
    __shared__ uint32_t As[BK * ASTR];
    __shared__ uint32_t Bs[BK * BSTR];

    int tid = threadIdx.x;
    int lane = tid & 31, wid = tid >> 5;
    int wm = (wid & 1) * 64;       // warp M offset inside block
    int wn = (wid >> 1) * 32;      // warp N offset inside block
    int bm = blockIdx.y * BM, bn = blockIdx.x * BN;

    float acc[4][4][4];
    #pragma unroll
    for (int i = 0; i < 4; i++)
        #pragma unroll
        for (int j = 0; j < 4; j++)
            #pragma unroll
            for (int q = 0; q < 4; q++) acc[i][j][q] = 0.f;

    int a_row = tid >> 1;          // 0..127
    int a_kc  = (tid & 1) * 16;    // 0 or 16
    int b_krow = tid >> 3;         // 0..31
    int b_c    = (tid & 7) * 4;    // 0..28

    int lr = lane & 3;             // k-offset within fragment
    int lg = lane >> 2;            // 0..7

    for (int k0 = 0; k0 < K; k0 += BK) {
        // ---- stage A tile (transpose to [k][m], convert to tf32) ----
        const float* arow = A + (size_t)(bm + a_row) * K + k0 + a_kc;
        #pragma unroll
        for (int j = 0; j < 4; j++) {
            float4 v = *(const float4*)(arow + 4 * j);
            int kk = a_kc + 4 * j;
            As[(kk + 0) * ASTR + a_row] = f2tf32(v.x);
            As[(kk + 1) * ASTR + a_row] = f2tf32(v.y);
            As[(kk + 2) * ASTR + a_row] = f2tf32(v.z);
            As[(kk + 3) * ASTR + a_row] = f2tf32(v.w);
        }
        // ---- stage B tile ([k][n], tf32) ----
        const float* brow = Bmat + (size_t)(k0 + b_krow) * N + bn;
        #pragma unroll
        for (int j = 0; j < 4; j++) {
            float4 v = *(const float4*)(brow + b_c + 32 * j);
            uint32_t* p = &Bs[b_krow * BSTR + b_c + 32 * j];
            p[0] = f2tf32(v.x); p[1] = f2tf32(v.y);
            p[2] = f2tf32(v.z); p[3] = f2tf32(v.w);
        }
        __syncthreads();

        #pragma unroll
        for (int ks = 0; ks < 4; ks++) {
            int kb = ks * 8;
            uint32_t af[4][4], bf[4][2];
            #pragma unroll
            for (int i = 0; i < 4; i++) {
                const uint32_t* pa = &As[(kb + lr) * ASTR + wm + 16 * i + lg];
                af[i][0] = pa[0];
                af[i][1] = pa[8];
                af[i][2] = pa[4 * ASTR];
                af[i][3] = pa[4 * ASTR + 8];
            }
            #pragma unroll
            for (int j = 0; j < 4; j++) {
                const uint32_t* pb = &Bs[(kb + lr) * BSTR + wn + 8 * j + lg];
                bf[j][0] = pb[0];
                bf[j][1] = pb[4 * BSTR];
            }
            #pragma unroll
            for (int i = 0; i < 4; i++)
                #pragma unroll
                for (int j = 0; j < 4; j++) {
                    asm volatile(
                        "mma.sync.aligned.m16n8k8.row.col.f32.tf32.tf32.f32 "
                        "{%0,%1,%2,%3}, {%4,%5,%6,%7}, {%8,%9}, {%0,%1,%2,%3};"
                        : "+f"(acc[i][j][0]), "+f"(acc[i][j][1]),
                          "+f"(acc[i][j][2]), "+f"(acc[i][j][3])
                        : "r"(af[i][0]), "r"(af[i][1]), "r"(af[i][2]), "r"(af[i][3]),
                          "r"(bf[j][0]), "r"(bf[j][1]));
                }
        }
        __syncthreads();
    }

    // ---- epilogue ----
    #pragma unroll
    for (int i = 0; i < 4; i++) {
        int r0 = bm + wm + 16 * i + lg;
        #pragma unroll
        for (int j = 0; j < 4; j++) {
            int c0 = bn + wn + 8 * j + 2 * lr;
            float2 v0 = { acc[i][j][0], acc[i][j][1] };   // row r0
            float2 v1 = { acc[i][j][2], acc[i][j][3] };   // row r0+8
            if constexpr (EPI == 1) {
                float b0 = bias[c0], b1 = bias[c0 + 1];
                v0.x = softplusf(v0.x + b0); v0.y = softplusf(v0.y + b1);
                v1.x = softplusf(v1.x + b0); v1.y = softplusf(v1.y + b1);
            } else if constexpr (EPI == 2) {
                float2 r4a = *(const float2*)(resid + (size_t)r0 * N + c0);
                float2 r4b = *(const float2*)(resid + (size_t)(r0 + 8) * N + c0);
                v0.x += r4a.x; v0.y += r4a.y;
                v1.x += r4b.x; v1.y += r4b.y;
            }
            *(float2*)(C + (size_t)r0 * N + c0) = v0;
            *(float2*)(C + (size_t)(r0 + 8) * N + c0) = v1;
        }
    }
}

// ---------------------------------------------------------------------------
// Depthwise causal conv1d (taps=4, left pad 3) + bias + SiLU.
// ---------------------------------------------------------------------------
__global__ void conv_silu_kernel(const float* __restrict__ wconv,
                                 const float* __restrict__ bconv)
{
    size_t idx = (size_t)blockIdx.x * blockDim.x + threadIdx.x;
    if (idx >= (size_t)ROWS * DIN) return;
    int d = (int)(idx & (DIN - 1));
    size_t row = idx >> 11;
    int l = (int)(row & (L - 1));

    float w0 = wconv[d * 4 + 0], w1 = wconv[d * 4 + 1];
    float w2 = wconv[d * 4 + 2], w3 = wconv[d * 4 + 3];
    const float* base = g_xz + row * (size_t)(2 * DIN) + d;

    float s = bconv[d];
    s = fmaf(base[0], w3, s);
    if (l >= 1) s = fmaf(*(base - 1 * 2 * DIN), w2, s);
    if (l >= 2) s = fmaf(*(base - 2 * 2 * DIN), w1, s);
    if (l >= 3) s = fmaf(*(base - 3 * 2 * DIN), w0, s);

    float sig = 1.f / (1.f + __expf(-s));
    g_u[idx] = s * sig;
}

// ---------------------------------------------------------------------------
// Bseq / Cseq: tiled tall-skinny GEMM. One block = 16 rows, staged weights.
// ---------------------------------------------------------------------------
__global__ __launch_bounds__(256)
void bc_kernel(const float* __restrict__ wb, const float* __restrict__ wc)
{
    __shared__ float us[16][136];
    __shared__ float ws[128][32];

    int tid = threadIdx.x;
    int row0 = blockIdx.x * 16;
    int trow = tid >> 4;           // 0..15 output row
    int tn   = (tid & 15) * 2;     // 0..30 output col pair (B|C)

    int ur = tid >> 4;             // u load row
    int uc = (tid & 15) * 8;       // u load col base

    float a0 = 0.f, a1 = 0.f;

    for (int kb = 0; kb < DIN; kb += 128) {
        const float* up = g_u + (size_t)(row0 + ur) * DIN + kb + uc;
        *(float4*)&us[ur][uc]     = *(const float4*)(up);
        *(float4*)&us[ur][uc + 4] = *(const float4*)(up + 4);

        #pragma unroll
        for (int q = 0; q < 4; q++) {
            int fi = tid * 4 + q;       // 0..1023 float4 index
            int kk = fi >> 3;           // 0..127
            int part = fi & 7;          // 0..7
            const float* src = (part < 4)
                ? (wb + (size_t)(kb + kk) * NST + part * 4)
                : (wc + (size_t)(kb + kk) * NST + (part - 4) * 4);
            int col = (part < 4) ? part * 4 : 16 + (part - 4) * 4;
            *(float4*)&ws[kk][col] = *(const float4*)src;
        }
        __syncthreads();

        #pragma unroll 8
        for (int k = 0; k < 128; k++) {
            float uv = us[trow][k];
            float2 w2 = *(const float2*)&ws[k][tn];
            a0 = fmaf(uv, w2.x, a0);
            a1 = fmaf(uv, w2.y, a1);
        }
        __syncthreads();
    }

    int r = row0 + trow;
    if (tn < 16) {
        g_Bseq[(size_t)r * NST + tn]     = a0;
        g_Bseq[(size_t)r * NST + tn + 1] = a1;
    } else {
        g_Cseq[(size_t)r * NST + tn - 16] = a0;
        g_Cseq[(size_t)r * NST + tn - 15] = a1;
    }
}

// ---------------------------------------------------------------------------
// Chunked selective scan (2 passes + combine)
// ---------------------------------------------------------------------------
template<bool PASS2>
__global__ void scan_kernel(const float* __restrict__ A_log,
                            const float* __restrict__ D_param)
{
    int gid = blockIdx.x * blockDim.x + threadIdx.x;
    if (gid >= BSZ * DIN * NCH) return;
    int d = gid & (DIN - 1);
    int c = (gid >> 11) & (NCH - 1);
    int b = gid >> 15;

    float A[NST];
    #pragma unroll
    for (int n = 0; n < NST; n++) A[n] = -__expf(A_log[d * NST + n]);

    bool structured = true;
    #pragma unroll
    for (int n = 1; n < NST; n++) {
        float t = (float)(n + 1) * A[0];
        if (fabsf(A[n] - t) > 1e-4f * fabsf(t)) structured = false;
    }

    float h[NST], P[NST];
    #pragma unroll
    for (int n = 0; n < NST; n++) { h[n] = 0.f; P[n] = 1.f; }

    size_t sidx = ((size_t)((b * DIN + d) * NCH + c)) * NST;
    if constexpr (PASS2) {
        #pragma unroll
        for (int n = 0; n < NST; n += 4) {
            float4 v = *(const float4*)(g_H0 + sidx + n);
            h[n] = v.x; h[n+1] = v.y; h[n+2] = v.z; h[n+3] = v.w;
        }
    }
    float Dp = PASS2 ? D_param[d] : 0.f;

    size_t row0 = (size_t)b * L + (size_t)c * LC;
    for (int t = 0; t < LC; t++) {
        size_t row = row0 + t;
        float dl = g_delta[row * DIN + d];
        float uv = g_u[row * DIN + d];
        float du = dl * uv;

        float Bv[NST];
        #pragma unroll
        for (int n = 0; n < NST; n += 4) {
            float4 v = *(const float4*)(g_Bseq + row * NST + n);
            Bv[n] = v.x; Bv[n+1] = v.y; Bv[n+2] = v.z; Bv[n+3] = v.w;
        }

        float e[NST];
        if (structured) {
            float e1 = __expf(dl * A[0]);
            float e2 = e1 * e1, e4 = e2 * e2, e8 = e4 * e4;
            e[0]  = e1;           e[1]  = e2;           e[2]  = e2 * e1;
            e[3]  = e4;           e[4]  = e4 * e1;      e[5]  = e4 * e2;
            e[6]  = e4 * e2 * e1; e[7]  = e8;           e[8]  = e8 * e1;
            e[9]  = e8 * e2;      e[10] = e8 * e2 * e1; e[11] = e8 * e4;
            e[12] = e8 * e4 * e1; e[13] = e8 * e4 * e2; e[14] = e8 * e4 * e2 * e1;
            e[15] = e8 * e8;
        } else {
            #pragma unroll
            for (int n = 0; n < NST; n++) e[n] = __expf(dl * A[n]);
        }

        #pragma unroll
        for (int n = 0; n < NST; n++) {
            h[n] = fmaf(e[n], h[n], du * Bv[n]);
            if constexpr (!PASS2) P[n] *= e[n];
        }

        if constexpr (PASS2) {
            float Cv[NST];
            #pragma unroll
            for (int n = 0; n < NST; n += 4) {
                float4 v = *(const float4*)(g_Cseq + row * NST + n);
                Cv[n] = v.x; Cv[n+1] = v.y; Cv[n+2] = v.z; Cv[n+3] = v.w;
            }
            float y = Dp * uv;
            #pragma unroll
            for (int n = 0; n < NST; n++) y = fmaf(h[n], Cv[n], y);

            float z = g_xz[row * (size_t)(2 * DIN) + DIN + d];
            float sz = z / (1.f + __expf(-z));
            g_gate[row * DIN + d] = y * sz;
        }
    }

    if constexpr (!PASS2) {
        #pragma unroll
        for (int n = 0; n < NST; n += 4) {
            float4 vp = { P[n], P[n+1], P[n+2], P[n+3] };
            float4 vh = { h[n], h[n+1], h[n+2], h[n+3] };
            *(float4*)(g_P + sidx + n)    = vp;
            *(float4*)(g_hloc + sidx + n) = vh;
        }
    }
}

__global__ void scan_combine_kernel()
{
    int gid = blockIdx.x * blockDim.x + threadIdx.x;
    if (gid >= BSZ * DIN) return;
    size_t base = (size_t)gid * NCH * NST;
    float H[NST];
    #pragma unroll
    for (int n = 0; n < NST; n++) H[n] = 0.f;
    for (int c = 0; c < NCH; c++) {
        size_t idx = base + (size_t)c * NST;
        #pragma unroll
        for (int n = 0; n < NST; n += 4) {
            float4 v = { H[n], H[n+1], H[n+2], H[n+3] };
            *(float4*)(g_H0 + idx + n) = v;
        }
        #pragma unroll
        for (int n = 0; n < NST; n++)
            H[n] = fmaf(g_P[idx + n], H[n], g_hloc[idx + n]);
    }
}

// ---------------------------------------------------------------------------
// Launch
// ---------------------------------------------------------------------------
extern "C" void kernel_launch(void* const* d_in, const int* in_sizes, int n_in,
                              void* d_out, int out_size)
{
    const float* x       = (const float*)d_in[0];
    const float* w_norm  = (const float*)d_in[1];
    const float* b_norm  = (const float*)d_in[2];
    const float* w_in    = (const float*)d_in[3];
    const float* w_conv  = (const float*)d_in[4];
    const float* b_conv  = (const float*)d_in[5];
    const float* A_log   = (const float*)d_in[6];
    const float* w_b     = (const float*)d_in[7];
    const float* w_c     = (const float*)d_in[8];
    const float* w_delta = (const float*)d_in[9];
    const float* b_delta = (const float*)d_in[10];
    const float* D_param = (const float*)d_in[11];
    const float* w_out   = (const float*)d_in[12];
    float* out = (float*)d_out;

    // 1. LayerNorm
    ln_kernel<<<ROWS, 256>>>(x, w_norm, b_norm);

    // 2. xz = xn @ w_in   (4096 x 4096, K=1024) -- TF32 tensor core
    tgemm_kernel<ROWS, 2 * DIN, DM, 0, 0, 0>
        <<<dim3((2 * DIN) / 128, ROWS / 128), 256>>>(w_in, nullptr, nullptr, nullptr);

    // 3. depthwise causal conv + bias + silu -> u
    conv_silu_kernel<<<(int)(((size_t)ROWS * DIN + 255) / 256), 256>>>(w_conv, b_conv);

    // 4a. Bseq/Cseq = u @ w_b, u @ w_c (tiled)
    bc_kernel<<<ROWS / 16, 256>>>(w_b, w_c);

    // 4b. delta = softplus(u @ w_delta + b_delta) -- TF32 tensor core
    tgemm_kernel<ROWS, DIN, DIN, 1, 1, 1>
        <<<dim3(DIN / 128, ROWS / 128), 256>>>(w_delta, b_delta, nullptr, nullptr);

    // 5. chunked selective scan
    scan_kernel<false><<<(BSZ * DIN * NCH) / 256, 256>>>(A_log, D_param);
    scan_combine_kernel<<<(BSZ * DIN) / 256, 256>>>();
    scan_kernel<true><<<(BSZ * DIN * NCH) / 256, 256>>>(A_log, D_param);

    // 6. out = gate @ w_out + residual -- TF32 tensor core
    tgemm_kernel<ROWS, DM, DIN, 2, 2, 2>
        <<<dim3(DM / 128, ROWS / 128), 256>>>(w_out, nullptr, x, out);
}

// round 5
// speedup vs baseline: 2.3653x; 1.1539x over previous
#include <cuda_runtime.h>
#include <cstdint>

// ---------------------------------------------------------------------------
// Problem constants
// ---------------------------------------------------------------------------
constexpr int BSZ = 2;
constexpr int L   = 2048;
constexpr int DM  = 1024;
constexpr int DIN = 2048;
constexpr int NST = 16;
constexpr int ROWS = BSZ * L;    // 4096
constexpr int NCH  = 16;
constexpr int LC   = L / NCH;    // 128

// ---------------------------------------------------------------------------
// Scratch (static device globals)
// ---------------------------------------------------------------------------
__device__ float g_xn   [(size_t)ROWS * DM];        // tf32-rounded layernorm out
__device__ float g_xz   [(size_t)ROWS * 2 * DIN];
__device__ float g_u    [(size_t)ROWS * DIN];       // fp32 (scan/bc consumers)
__device__ float g_u32  [(size_t)ROWS * DIN];       // tf32-rounded copy (GEMM A)
__device__ float g_delta[(size_t)ROWS * DIN];
__device__ float g_Bseq [(size_t)ROWS * NST];
__device__ float g_Cseq [(size_t)ROWS * NST];
__device__ float g_gate [(size_t)ROWS * DIN];       // tf32-rounded (GEMM A only)
__device__ float g_P    [(size_t)BSZ * DIN * NCH * NST];
__device__ float g_hloc [(size_t)BSZ * DIN * NCH * NST];
__device__ float g_H0   [(size_t)BSZ * DIN * NCH * NST];
// transposed + tf32-rounded weights ([N][K] layouts)
__device__ float g_wtin [(size_t)(2 * DIN) * DM];
__device__ float g_wtd  [(size_t)DIN * DIN];
__device__ float g_wto  [(size_t)DM * DIN];

// ---------------------------------------------------------------------------
// Helpers
// ---------------------------------------------------------------------------
__device__ __forceinline__ uint32_t smem_u32(const void* p)
{
    uint32_t a;
    asm("{ .reg .u64 t; cvta.to.shared.u64 t, %1; cvt.u32.u64 %0, t; }"
        : "=r"(a) : "l"(p));
    return a;
}

__device__ __forceinline__ uint32_t f2tf32(float f)
{
    uint32_t r;
    asm("cvt.rna.tf32.f32 %0, %1;" : "=r"(r) : "f"(f));
    return r;
}

__device__ __forceinline__ float softplusf(float v)
{
    return v > 20.f ? v : log1pf(expf(v));
}

#define CP_ASYNC16(dst, src) \
    asm volatile("cp.async.cg.shared.global [%0], [%1], 16;" \
                 :: "r"(dst), "l"(src) : "memory")
#define CP_COMMIT() asm volatile("cp.async.commit_group;" ::: "memory")
#define CP_WAIT1()  asm volatile("cp.async.wait_group 1;" ::: "memory")

// ---------------------------------------------------------------------------
// LayerNorm: one block per row; output tf32-rounded (GEMM1 is sole consumer)
// ---------------------------------------------------------------------------
__global__ void ln_kernel(const float* __restrict__ x,
                          const float* __restrict__ w,
                          const float* __restrict__ b)
{
    __shared__ float sh[8];
    int row = blockIdx.x;
    const float* xr = x + (size_t)row * DM;
    int i0 = threadIdx.x * 4;
    float4 v = *(const float4*)(xr + i0);
    int lane = threadIdx.x & 31, wid = threadIdx.x >> 5;

    float s = v.x + v.y + v.z + v.w;
    #pragma unroll
    for (int o = 16; o > 0; o >>= 1) s += __shfl_down_sync(0xffffffffu, s, o);
    if (lane == 0) sh[wid] = s;
    __syncthreads();
    float t = (threadIdx.x < 8) ? sh[threadIdx.x] : 0.f;
    if (wid == 0) {
        #pragma unroll
        for (int o = 4; o > 0; o >>= 1) t += __shfl_down_sync(0xffffffffu, t, o);
        if (lane == 0) sh[0] = t;
    }
    __syncthreads();
    float mu = sh[0] * (1.f / DM);
    __syncthreads();

    float d0 = v.x - mu, d1 = v.y - mu, d2 = v.z - mu, d3 = v.w - mu;
    float ss = d0*d0 + d1*d1 + d2*d2 + d3*d3;
    #pragma unroll
    for (int o = 16; o > 0; o >>= 1) ss += __shfl_down_sync(0xffffffffu, ss, o);
    if (lane == 0) sh[wid] = ss;
    __syncthreads();
    t = (threadIdx.x < 8) ? sh[threadIdx.x] : 0.f;
    if (wid == 0) {
        #pragma unroll
        for (int o = 4; o > 0; o >>= 1) t += __shfl_down_sync(0xffffffffu, t, o);
        if (lane == 0) sh[0] = t;
    }
    __syncthreads();
    float rstd = rsqrtf(sh[0] * (1.f / DM) + 1e-5f);

    float4 wv = *(const float4*)(w + i0);
    float4 bv = *(const float4*)(b + i0);
    uint4 o4;
    o4.x = f2tf32(d0 * rstd * wv.x + bv.x);
    o4.y = f2tf32(d1 * rstd * wv.y + bv.y);
    o4.z = f2tf32(d2 * rstd * wv.z + bv.z);
    o4.w = f2tf32(d3 * rstd * wv.w + bv.w);
    *(uint4*)(g_xn + (size_t)row * DM + i0) = o4;
}

// ---------------------------------------------------------------------------
// Weight transpose + tf32 round: out[c][r] = tf32(in[r][c]); in is [R][Cn]
// ---------------------------------------------------------------------------
__global__ void transpose_tf32_kernel(const float* __restrict__ in,
                                      float* __restrict__ out, int R, int Cn)
{
    __shared__ float tile[32][33];
    int c0 = blockIdx.x * 32, r0 = blockIdx.y * 32;
    #pragma unroll
    for (int i = 0; i < 4; i++)
        tile[threadIdx.y + 8 * i][threadIdx.x] =
            in[(size_t)(r0 + threadIdx.y + 8 * i) * Cn + c0 + threadIdx.x];
    __syncthreads();
    #pragma unroll
    for (int i = 0; i < 4; i++) {
        float v = tile[threadIdx.x][threadIdx.y + 8 * i];
        out[(size_t)(c0 + threadIdx.y + 8 * i) * R + r0 + threadIdx.x] =
            __uint_as_float(f2tf32(v));
    }
}

// ---------------------------------------------------------------------------
// TF32 mma.sync GEMM with cp.async 3-stage pipeline.
// C[M, NTOT] = A[M, K] * Bt^T   (A, Bt pre-rounded tf32; Bt is [NTOT][K])
// BM=128 BN=128 BK=32, 256 threads (8 warps: 2 M x 4 N; warp tile 64x32).
// EPI: 0 none, 1 bias+softplus, 2 +residual.
// ---------------------------------------------------------------------------
constexpr int GPAD   = 36;                    // smem row stride (floats)
constexpr int GSTAGE = 2 * 128 * GPAD;        // floats per stage (A+B)
constexpr int GEMM_DSMEM = 3 * GSTAGE * 4;    // bytes

template<int NTOT, int K, int EPI, int ASEL, int CSEL>
__global__ __launch_bounds__(256, 2)
void tc_gemm(const float* __restrict__ Bt,
             const float* __restrict__ bias,
             const float* __restrict__ resid,
             float* __restrict__ Cext)
{
    const float* A = (ASEL == 0) ? g_xn : (ASEL == 1) ? g_u32 : g_gate;
    float* C = (CSEL == 0) ? g_xz : (CSEL == 1) ? g_delta : Cext;

    extern __shared__ float dsm[];
    uint32_t smem0 = smem_u32(dsm);

    int tid = threadIdx.x;
    int lane = tid & 31, wid = tid >> 5;
    int wm = (wid & 1) * 64;
    int wn = (wid >> 1) * 32;
    int bm = blockIdx.y * 128;
    int bn = blockIdx.x * 128;
    int lr = lane & 3;             // k within quad
    int lg = lane >> 2;            // m/n group

    const float* Ag0 = A  + (size_t)bm * K;
    const float* Bg0 = Bt + (size_t)bn * K;

    int ldr = tid >> 3;            // 0..31 -> two rows per q step (128 rows / 4q)
    int ldc = (tid & 7) * 4;       // chunk column (floats)

    constexpr int KT = K / 32;

    // ---- stage issue helper (as lambda) ----
    auto issue = [&](int stage, int kt) {
        uint32_t sA = smem0 + (uint32_t)stage * GSTAGE * 4;
        uint32_t sB = sA + 128 * GPAD * 4;
        const float* Ag = Ag0 + kt * 32;
        const float* Bg = Bg0 + kt * 32;
        #pragma unroll
        for (int q = 0; q < 4; q++) {
            int r = q * 32 + ldr;
            CP_ASYNC16(sA + (uint32_t)(r * GPAD + ldc) * 4, Ag + (size_t)r * K + ldc);
        }
        #pragma unroll
        for (int q = 0; q < 4; q++) {
            int r = q * 32 + ldr;
            CP_ASYNC16(sB + (uint32_t)(r * GPAD + ldc) * 4, Bg + (size_t)r * K + ldc);
        }
    };

    float acc[4][4][4];
    #pragma unroll
    for (int i = 0; i < 4; i++)
        #pragma unroll
        for (int j = 0; j < 4; j++)
            #pragma unroll
            for (int q = 0; q < 4; q++) acc[i][j][q] = 0.f;

    // prologue: stages 0,1
    issue(0, 0); CP_COMMIT();
    issue(1, 1); CP_COMMIT();

    for (int kt = 0; kt < KT; kt++) {
        CP_WAIT1();
        __syncthreads();

        const float* As = dsm + (kt % 3) * GSTAGE;
        const float* Bs = As + 128 * GPAD;

        #pragma unroll
        for (int ks = 0; ks < 4; ks++) {
            int kb = ks * 8 + lr;
            uint32_t af[4][4], bf[4][2];
            #pragma unroll
            for (int i = 0; i < 4; i++) {
                const float* pa = As + (wm + 16 * i + lg) * GPAD + kb;
                af[i][0] = __float_as_uint(pa[0]);
                af[i][1] = __float_as_uint(pa[8 * GPAD]);
                af[i][2] = __float_as_uint(pa[4]);
                af[i][3] = __float_as_uint(pa[8 * GPAD + 4]);
            }
            #pragma unroll
            for (int j = 0; j < 4; j++) {
                const float* pb = Bs + (wn + 8 * j + lg) * GPAD + kb;
                bf[j][0] = __float_as_uint(pb[0]);
                bf[j][1] = __float_as_uint(pb[4]);
            }
            #pragma unroll
            for (int i = 0; i < 4; i++)
                #pragma unroll
                for (int j = 0; j < 4; j++) {
                    asm volatile(
                        "mma.sync.aligned.m16n8k8.row.col.f32.tf32.tf32.f32 "
                        "{%0,%1,%2,%3}, {%4,%5,%6,%7}, {%8,%9}, {%0,%1,%2,%3};"
                        : "+f"(acc[i][j][0]), "+f"(acc[i][j][1]),
                          "+f"(acc[i][j][2]), "+f"(acc[i][j][3])
                        : "r"(af[i][0]), "r"(af[i][1]), "r"(af[i][2]), "r"(af[i][3]),
                          "r"(bf[j][0]), "r"(bf[j][1]));
                }
        }
        __syncthreads();
        if (kt + 2 < KT) issue((kt + 2) % 3, kt + 2);
        CP_COMMIT();
    }

    // ---- epilogue ----
    #pragma unroll
    for (int i = 0; i < 4; i++) {
        int r0 = bm + wm + 16 * i + lg;
        #pragma unroll
        for (int j = 0; j < 4; j++) {
            int c0 = bn + wn + 8 * j + 2 * lr;
            float2 v0 = { acc[i][j][0], acc[i][j][1] };
            float2 v1 = { acc[i][j][2], acc[i][j][3] };
            if constexpr (EPI == 1) {
                float b0 = bias[c0], b1 = bias[c0 + 1];
                v0.x = softplusf(v0.x + b0); v0.y = softplusf(v0.y + b1);
                v1.x = softplusf(v1.x + b0); v1.y = softplusf(v1.y + b1);
            } else if constexpr (EPI == 2) {
                float2 ra = *(const float2*)(resid + (size_t)r0 * NTOT + c0);
                float2 rb = *(const float2*)(resid + (size_t)(r0 + 8) * NTOT + c0);
                v0.x += ra.x; v0.y += ra.y;
                v1.x += rb.x; v1.y += rb.y;
            }
            *(float2*)(C + (size_t)r0 * NTOT + c0) = v0;
            *(float2*)(C + (size_t)(r0 + 8) * NTOT + c0) = v1;
        }
    }
}

// ---------------------------------------------------------------------------
// Depthwise causal conv1d + bias + SiLU. Writes fp32 u and tf32 copy.
// ---------------------------------------------------------------------------
__global__ void conv_silu_kernel(const float* __restrict__ wconv,
                                 const float* __restrict__ bconv)
{
    size_t idx = (size_t)blockIdx.x * blockDim.x + threadIdx.x;
    if (idx >= (size_t)ROWS * DIN) return;
    int d = (int)(idx & (DIN - 1));
    size_t row = idx >> 11;
    int l = (int)(row & (L - 1));

    float w0 = wconv[d * 4 + 0], w1 = wconv[d * 4 + 1];
    float w2 = wconv[d * 4 + 2], w3 = wconv[d * 4 + 3];
    const float* base = g_xz + row * (size_t)(2 * DIN) + d;

    float s = bconv[d];
    s = fmaf(base[0], w3, s);
    if (l >= 1) s = fmaf(*(base - 1 * 2 * DIN), w2, s);
    if (l >= 2) s = fmaf(*(base - 2 * 2 * DIN), w1, s);
    if (l >= 3) s = fmaf(*(base - 3 * 2 * DIN), w0, s);

    float sig = 1.f / (1.f + __expf(-s));
    float u = s * sig;
    g_u[idx] = u;
    g_u32[idx] = __uint_as_float(f2tf32(u));
}

// ---------------------------------------------------------------------------
// Bseq / Cseq (fp32, exact — protects rel_err budget)
// ---------------------------------------------------------------------------
__global__ __launch_bounds__(256)
void bc_kernel(const float* __restrict__ wb, const float* __restrict__ wc)
{
    __shared__ float us[16][136];
    __shared__ float ws[128][32];

    int tid = threadIdx.x;
    int row0 = blockIdx.x * 16;
    int trow = tid >> 4;
    int tn   = (tid & 15) * 2;
    int ur = tid >> 4;
    int uc = (tid & 15) * 8;

    float a0 = 0.f, a1 = 0.f;

    for (int kb = 0; kb < DIN; kb += 128) {
        const float* up = g_u + (size_t)(row0 + ur) * DIN + kb + uc;
        *(float4*)&us[ur][uc]     = *(const float4*)(up);
        *(float4*)&us[ur][uc + 4] = *(const float4*)(up + 4);

        #pragma unroll
        for (int q = 0; q < 4; q++) {
            int fi = tid * 4 + q;
            int kk = fi >> 3;
            int part = fi & 7;
            const float* src = (part < 4)
                ? (wb + (size_t)(kb + kk) * NST + part * 4)
                : (wc + (size_t)(kb + kk) * NST + (part - 4) * 4);
            int col = (part < 4) ? part * 4 : 16 + (part - 4) * 4;
            *(float4*)&ws[kk][col] = *(const float4*)src;
        }
        __syncthreads();

        #pragma unroll 8
        for (int k = 0; k < 128; k++) {
            float uv = us[trow][k];
            float2 w2 = *(const float2*)&ws[k][tn];
            a0 = fmaf(uv, w2.x, a0);
            a1 = fmaf(uv, w2.y, a1);
        }
        __syncthreads();
    }

    int r = row0 + trow;
    if (tn < 16) {
        g_Bseq[(size_t)r * NST + tn]     = a0;
        g_Bseq[(size_t)r * NST + tn + 1] = a1;
    } else {
        g_Cseq[(size_t)r * NST + tn - 16] = a0;
        g_Cseq[(size_t)r * NST + tn - 15] = a1;
    }
}

// ---------------------------------------------------------------------------
// Chunked selective scan (pass2 writes tf32-rounded gate)
// ---------------------------------------------------------------------------
template<bool PASS2>
__global__ void scan_kernel(const float* __restrict__ A_log,
                            const float* __restrict__ D_param)
{
    int gid = blockIdx.x * blockDim.x + threadIdx.x;
    if (gid >= BSZ * DIN * NCH) return;
    int d = gid & (DIN - 1);
    int c = (gid >> 11) & (NCH - 1);
    int b = gid >> 15;

    float A[NST];
    #pragma unroll
    for (int n = 0; n < NST; n++) A[n] = -__expf(A_log[d * NST + n]);

    bool structured = true;
    #pragma unroll
    for (int n = 1; n < NST; n++) {
        float t = (float)(n + 1) * A[0];
        if (fabsf(A[n] - t) > 1e-4f * fabsf(t)) structured = false;
    }

    float h[NST], P[NST];
    #pragma unroll
    for (int n = 0; n < NST; n++) { h[n] = 0.f; P[n] = 1.f; }

    size_t sidx = ((size_t)((b * DIN + d) * NCH + c)) * NST;
    if constexpr (PASS2) {
        #pragma unroll
        for (int n = 0; n < NST; n += 4) {
            float4 v = *(const float4*)(g_H0 + sidx + n);
            h[n] = v.x; h[n+1] = v.y; h[n+2] = v.z; h[n+3] = v.w;
        }
    }
    float Dp = PASS2 ? D_param[d] : 0.f;

    size_t row0 = (size_t)b * L + (size_t)c * LC;
    for (int t = 0; t < LC; t++) {
        size_t row = row0 + t;
        float dl = g_delta[row * DIN + d];
        float uv = g_u[row * DIN + d];
        float du = dl * uv;

        float Bv[NST];
        #pragma unroll
        for (int n = 0; n < NST; n += 4) {
            float4 v = *(const float4*)(g_Bseq + row * NST + n);
            Bv[n] = v.x; Bv[n+1] = v.y; Bv[n+2] = v.z; Bv[n+3] = v.w;
        }

        float e[NST];
        if (structured) {
            float e1 = __expf(dl * A[0]);
            float e2 = e1 * e1, e4 = e2 * e2, e8 = e4 * e4;
            e[0]  = e1;           e[1]  = e2;           e[2]  = e2 * e1;
            e[3]  = e4;           e[4]  = e4 * e1;      e[5]  = e4 * e2;
            e[6]  = e4 * e2 * e1; e[7]  = e8;           e[8]  = e8 * e1;
            e[9]  = e8 * e2;      e[10] = e8 * e2 * e1; e[11] = e8 * e4;
            e[12] = e8 * e4 * e1; e[13] = e8 * e4 * e2; e[14] = e8 * e4 * e2 * e1;
            e[15] = e8 * e8;
        } else {
            #pragma unroll
            for (int n = 0; n < NST; n++) e[n] = __expf(dl * A[n]);
        }

        #pragma unroll
        for (int n = 0; n < NST; n++) {
            h[n] = fmaf(e[n], h[n], du * Bv[n]);
            if constexpr (!PASS2) P[n] *= e[n];
        }

        if constexpr (PASS2) {
            float Cv[NST];
            #pragma unroll
            for (int n = 0; n < NST; n += 4) {
                float4 v = *(const float4*)(g_Cseq + row * NST + n);
                Cv[n] = v.x; Cv[n+1] = v.y; Cv[n+2] = v.z; Cv[n+3] = v.w;
            }
            float y = Dp * uv;
            #pragma unroll
            for (int n = 0; n < NST; n++) y = fmaf(h[n], Cv[n], y);

            float z = g_xz[row * (size_t)(2 * DIN) + DIN + d];
            float sz = z / (1.f + __expf(-z));
            g_gate[row * DIN + d] = __uint_as_float(f2tf32(y * sz));
        }
    }

    if constexpr (!PASS2) {
        #pragma unroll
        for (int n = 0; n < NST; n += 4) {
            float4 vp = { P[n], P[n+1], P[n+2], P[n+3] };
            float4 vh = { h[n], h[n+1], h[n+2], h[n+3] };
            *(float4*)(g_P + sidx + n)    = vp;
            *(float4*)(g_hloc + sidx + n) = vh;
        }
    }
}

__global__ void scan_combine_kernel()
{
    int gid = blockIdx.x * blockDim.x + threadIdx.x;
    if (gid >= BSZ * DIN) return;
    size_t base = (size_t)gid * NCH * NST;
    float H[NST];
    #pragma unroll
    for (int n = 0; n < NST; n++) H[n] = 0.f;
    for (int c = 0; c < NCH; c++) {
        size_t idx = base + (size_t)c * NST;
        #pragma unroll
        for (int n = 0; n < NST; n += 4) {
            float4 v = { H[n], H[n+1], H[n+2], H[n+3] };
            *(float4*)(g_H0 + idx + n) = v;
        }
        #pragma unroll
        for (int n = 0; n < NST; n++)
            H[n] = fmaf(g_P[idx + n], H[n], g_hloc[idx + n]);
    }
}

// ---------------------------------------------------------------------------
// Launch
// ---------------------------------------------------------------------------
extern "C" void kernel_launch(void* const* d_in, const int* in_sizes, int n_in,
                              void* d_out, int out_size)
{
    const float* x       = (const float*)d_in[0];
    const float* w_norm  = (const float*)d_in[1];
    const float* b_norm  = (const float*)d_in[2];
    const float* w_in    = (const float*)d_in[3];
    const float* w_conv  = (const float*)d_in[4];
    const float* b_conv  = (const float*)d_in[5];
    const float* A_log   = (const float*)d_in[6];
    const float* w_b     = (const float*)d_in[7];
    const float* w_c     = (const float*)d_in[8];
    const float* w_delta = (const float*)d_in[9];
    const float* b_delta = (const float*)d_in[10];
    const float* D_param = (const float*)d_in[11];
    const float* w_out   = (const float*)d_in[12];
    float* out = (float*)d_out;

    // opt into >48KB dynamic smem (idempotent, not a stream op)
    cudaFuncSetAttribute(tc_gemm<2 * DIN, DM, 0, 0, 0>,
                         cudaFuncAttributeMaxDynamicSharedMemorySize, GEMM_DSMEM);
    cudaFuncSetAttribute(tc_gemm<DIN, DIN, 1, 1, 1>,
                         cudaFuncAttributeMaxDynamicSharedMemorySize, GEMM_DSMEM);
    cudaFuncSetAttribute(tc_gemm<DM, DIN, 2, 2, 2>,
                         cudaFuncAttributeMaxDynamicSharedMemorySize, GEMM_DSMEM);

    float *wt_in, *wt_d, *wt_o;
    cudaGetSymbolAddress((void**)&wt_in, g_wtin);
    cudaGetSymbolAddress((void**)&wt_d,  g_wtd);
    cudaGetSymbolAddress((void**)&wt_o,  g_wto);

    // 0. weight transposes (+ tf32 rounding)
    transpose_tf32_kernel<<<dim3((2 * DIN) / 32, DM / 32), dim3(32, 8)>>>(w_in, wt_in, DM, 2 * DIN);
    transpose_tf32_kernel<<<dim3(DIN / 32, DIN / 32), dim3(32, 8)>>>(w_delta, wt_d, DIN, DIN);
    transpose_tf32_kernel<<<dim3(DM / 32, DIN / 32), dim3(32, 8)>>>(w_out, wt_o, DIN, DM);

    // 1. LayerNorm (tf32-rounded output)
    ln_kernel<<<ROWS, 256>>>(x, w_norm, b_norm);

    // 2. xz = xn @ w_in
    tc_gemm<2 * DIN, DM, 0, 0, 0>
        <<<dim3((2 * DIN) / 128, ROWS / 128), 256, GEMM_DSMEM>>>(wt_in, nullptr, nullptr, nullptr);

    // 3. conv + silu -> u (fp32 + tf32 copy)
    conv_silu_kernel<<<(int)(((size_t)ROWS * DIN + 255) / 256), 256>>>(w_conv, b_conv);

    // 4a. Bseq/Cseq (fp32 exact)
    bc_kernel<<<ROWS / 16, 256>>>(w_b, w_c);

    // 4b. delta = softplus(u @ w_delta + b_delta)
    tc_gemm<DIN, DIN, 1, 1, 1>
        <<<dim3(DIN / 128, ROWS / 128), 256, GEMM_DSMEM>>>(wt_d, b_delta, nullptr, nullptr);

    // 5. chunked selective scan
    scan_kernel<false><<<(BSZ * DIN * NCH) / 256, 256>>>(A_log, D_param);
    scan_combine_kernel<<<(BSZ * DIN) / 256, 256>>>();
    scan_kernel<true><<<(BSZ * DIN * NCH) / 256, 256>>>(A_log, D_param);

    // 6. out = gate @ w_out + residual
    tc_gemm<DM, DIN, 2, 2, 2>
        <<<dim3(DM / 128, ROWS / 128), 256, GEMM_DSMEM>>>(wt_o, nullptr, x, out);
}

// round 6
// speedup vs baseline: 3.4332x; 1.4515x over previous
#include <cuda_runtime.h>
#include <cuda_fp16.h>
#include <cstdint>

// ---------------------------------------------------------------------------
// Problem constants
// ---------------------------------------------------------------------------
constexpr int BSZ = 2;
constexpr int L   = 2048;
constexpr int DM  = 1024;
constexpr int DIN = 2048;
constexpr int NST = 16;
constexpr int ROWS = BSZ * L;    // 4096
constexpr int NCH  = 16;
constexpr int LC   = L / NCH;    // 128

// ---------------------------------------------------------------------------
// Scratch (static device globals)
// ---------------------------------------------------------------------------
__device__ __half g_xnh [(size_t)ROWS * DM];        // fp16 layernorm out (GEMM1 A)
__device__ float  g_xz  [(size_t)ROWS * 2 * DIN];
__device__ float  g_u   [(size_t)ROWS * DIN];       // fp32 (scan/bc)
__device__ __half g_uh  [(size_t)ROWS * DIN];       // fp16 copy (GEMM2 A)
__device__ float  g_delta[(size_t)ROWS * DIN];
__device__ float  g_Bseq [(size_t)ROWS * NST];
__device__ float  g_Cseq [(size_t)ROWS * NST];
__device__ __half g_gateh[(size_t)ROWS * DIN];      // fp16 gate (GEMM3 A)
__device__ float  g_P    [(size_t)BSZ * DIN * NCH * NST];
__device__ float  g_hloc [(size_t)BSZ * DIN * NCH * NST];
__device__ float  g_H0   [(size_t)BSZ * DIN * NCH * NST];
// transposed fp16 weights ([N][K])
__device__ __half g_wtin [(size_t)(2 * DIN) * DM];
__device__ __half g_wtd  [(size_t)DIN * DIN];
__device__ __half g_wto  [(size_t)DM * DIN];

// ---------------------------------------------------------------------------
// Helpers
// ---------------------------------------------------------------------------
__device__ __forceinline__ uint32_t smem_u32(const void* p)
{
    uint32_t a;
    asm("{ .reg .u64 t; cvta.to.shared.u64 t, %1; cvt.u32.u64 %0, t; }"
        : "=r"(a) : "l"(p));
    return a;
}

__device__ __forceinline__ float softplusf(float v)
{
    return v > 20.f ? v : log1pf(expf(v));
}

#define CP_ASYNC16(dst, src) \
    asm volatile("cp.async.cg.shared.global [%0], [%1], 16;" \
                 :: "r"(dst), "l"(src) : "memory")
#define CP_COMMIT() asm volatile("cp.async.commit_group;" ::: "memory")
#define CP_WAIT1()  asm volatile("cp.async.wait_group 1;" ::: "memory")

#define LDMATRIX_X4(r0, r1, r2, r3, addr) \
    asm volatile("ldmatrix.sync.aligned.m8n8.x4.shared.b16 {%0,%1,%2,%3}, [%4];" \
                 : "=r"(r0), "=r"(r1), "=r"(r2), "=r"(r3) : "r"(addr))

#define MMA_F16(c0, c1, c2, c3, a0, a1, a2, a3, b0, b1) \
    asm volatile("mma.sync.aligned.m16n8k16.row.col.f32.f16.f16.f32 " \
                 "{%0,%1,%2,%3}, {%4,%5,%6,%7}, {%8,%9}, {%0,%1,%2,%3};" \
                 : "+f"(c0), "+f"(c1), "+f"(c2), "+f"(c3) \
                 : "r"(a0), "r"(a1), "r"(a2), "r"(a3), "r"(b0), "r"(b1))

// ---------------------------------------------------------------------------
// LayerNorm: one block per row; fp16 output (GEMM1 is sole consumer)
// ---------------------------------------------------------------------------
__global__ void ln_kernel(const float* __restrict__ x,
                          const float* __restrict__ w,
                          const float* __restrict__ b)
{
    __shared__ float sh[8];
    int row = blockIdx.x;
    const float* xr = x + (size_t)row * DM;
    int i0 = threadIdx.x * 4;
    float4 v = *(const float4*)(xr + i0);
    int lane = threadIdx.x & 31, wid = threadIdx.x >> 5;

    float s = v.x + v.y + v.z + v.w;
    #pragma unroll
    for (int o = 16; o > 0; o >>= 1) s += __shfl_down_sync(0xffffffffu, s, o);
    if (lane == 0) sh[wid] = s;
    __syncthreads();
    float t = (threadIdx.x < 8) ? sh[threadIdx.x] : 0.f;
    if (wid == 0) {
        #pragma unroll
        for (int o = 4; o > 0; o >>= 1) t += __shfl_down_sync(0xffffffffu, t, o);
        if (lane == 0) sh[0] = t;
    }
    __syncthreads();
    float mu = sh[0] * (1.f / DM);
    __syncthreads();

    float d0 = v.x - mu, d1 = v.y - mu, d2 = v.z - mu, d3 = v.w - mu;
    float ss = d0*d0 + d1*d1 + d2*d2 + d3*d3;
    #pragma unroll
    for (int o = 16; o > 0; o >>= 1) ss += __shfl_down_sync(0xffffffffu, ss, o);
    if (lane == 0) sh[wid] = ss;
    __syncthreads();
    t = (threadIdx.x < 8) ? sh[threadIdx.x] : 0.f;
    if (wid == 0) {
        #pragma unroll
        for (int o = 4; o > 0; o >>= 1) t += __shfl_down_sync(0xffffffffu, t, o);
        if (lane == 0) sh[0] = t;
    }
    __syncthreads();
    float rstd = rsqrtf(sh[0] * (1.f / DM) + 1e-5f);

    float4 wv = *(const float4*)(w + i0);
    float4 bv = *(const float4*)(b + i0);
    __half2 h0 = __floats2half2_rn(d0 * rstd * wv.x + bv.x, d1 * rstd * wv.y + bv.y);
    __half2 h1 = __floats2half2_rn(d2 * rstd * wv.z + bv.z, d3 * rstd * wv.w + bv.w);
    uint2 o2 = { *(uint32_t*)&h0, *(uint32_t*)&h1 };
    *(uint2*)(g_xnh + (size_t)row * DM + i0) = o2;
}

// ---------------------------------------------------------------------------
// Weight transpose + fp16 round: out[c][r] = half(in[r][c]); in is [R][Cn]
// ---------------------------------------------------------------------------
__global__ void transpose_h_kernel(const float* __restrict__ in,
                                   __half* __restrict__ out, int R, int Cn)
{
    __shared__ float tile[32][33];
    int c0 = blockIdx.x * 32, r0 = blockIdx.y * 32;
    #pragma unroll
    for (int i = 0; i < 4; i++)
        tile[threadIdx.y + 8 * i][threadIdx.x] =
            in[(size_t)(r0 + threadIdx.y + 8 * i) * Cn + c0 + threadIdx.x];
    __syncthreads();
    #pragma unroll
    for (int i = 0; i < 4; i++) {
        float v = tile[threadIdx.x][threadIdx.y + 8 * i];
        out[(size_t)(c0 + threadIdx.y + 8 * i) * R + r0 + threadIdx.x] =
            __float2half_rn(v);
    }
}

// ---------------------------------------------------------------------------
// FP16 mma.sync GEMM with cp.async 3-stage pipeline + ldmatrix.
// C[M, NTOT] = A[M, K] * Bt^T   (A, Bt fp16; Bt is [NTOT][K])
// BM=128 BN=128 BK=32, 256 threads (8 warps: 2 M x 4 N; warp tile 64x32).
// EPI: 0 none, 1 bias+softplus, 2 +residual.
// ---------------------------------------------------------------------------
constexpr int PADH   = 40;                        // smem row stride (halves)
constexpr int STG_H  = 2 * 128 * PADH;            // halves per stage (A+B)
constexpr int GEMM_DSMEM = 3 * STG_H * 2;         // bytes (61440)

template<int NTOT, int K, int EPI, int ASEL, int CSEL>
__global__ __launch_bounds__(256, 2)
void tc_gemm(const __half* __restrict__ Bt,
             const float* __restrict__ bias,
             const float* __restrict__ resid,
             float* __restrict__ Cext)
{
    const __half* A = (ASEL == 0) ? g_xnh : (ASEL == 1) ? g_uh : g_gateh;
    float* C = (CSEL == 0) ? g_xz : (CSEL == 1) ? g_delta : Cext;

    extern __shared__ __half dsm[];
    uint32_t smem0 = smem_u32(dsm);

    int tid = threadIdx.x;
    int lane = tid & 31, wid = tid >> 5;
    int wm = (wid & 1) * 64;
    int wn = (wid >> 1) * 32;
    int bm = blockIdx.y * 128;
    int bn = blockIdx.x * 128;
    int lr = lane & 3;
    int lg = lane >> 2;

    const __half* Ag0 = A  + (size_t)bm * K;
    const __half* Bg0 = Bt + (size_t)bn * K;

    // cp.async mapping: chunk = q*256+tid; row = chunk>>2; c16 = chunk&3
    int ld_row = tid >> 2;            // base row per q (64 rows per q of 256 thr)
    int ld_c16 = (tid & 3) * 16;      // byte offset within 64B row

    // ldmatrix lane offsets (bytes, within a stage base)
    int a_lrow = ((lane >> 3) & 1) * 8 + (lane & 7);
    int a_lcol = (lane >> 4) * 8;
    int b_lrow = (lane >> 4) * 8 + (lane & 7);
    int b_lcol = ((lane >> 3) & 1) * 8;

    constexpr int KT = K / 32;

    auto issue = [&](int stage, int kt) {
        uint32_t sA = smem0 + (uint32_t)stage * STG_H * 2;
        uint32_t sB = sA + 128 * PADH * 2;
        const __half* Ag = Ag0 + kt * 32;
        const __half* Bg = Bg0 + kt * 32;
        #pragma unroll
        for (int q = 0; q < 2; q++) {
            int r = q * 64 + ld_row;
            CP_ASYNC16(sA + (uint32_t)(r * PADH * 2) + ld_c16,
                       (const char*)(Ag + (size_t)r * K) + ld_c16);
            CP_ASYNC16(sB + (uint32_t)(r * PADH * 2) + ld_c16,
                       (const char*)(Bg + (size_t)r * K) + ld_c16);
        }
    };

    float acc[4][4][4];
    #pragma unroll
    for (int i = 0; i < 4; i++)
        #pragma unroll
        for (int j = 0; j < 4; j++)
            #pragma unroll
            for (int q = 0; q < 4; q++) acc[i][j][q] = 0.f;

    issue(0, 0); CP_COMMIT();
    issue(1, 1); CP_COMMIT();

    for (int kt = 0; kt < KT; kt++) {
        CP_WAIT1();
        __syncthreads();

        uint32_t sA = smem0 + (uint32_t)(kt % 3) * STG_H * 2;
        uint32_t sB = sA + 128 * PADH * 2;

        #pragma unroll
        for (int kc = 0; kc < 2; kc++) {
            uint32_t af[4][4], bf[2][4];
            #pragma unroll
            for (int i = 0; i < 4; i++) {
                uint32_t a = sA + (uint32_t)((wm + 16 * i + a_lrow) * PADH
                                             + a_lcol + kc * 16) * 2;
                LDMATRIX_X4(af[i][0], af[i][1], af[i][2], af[i][3], a);
            }
            #pragma unroll
            for (int jj = 0; jj < 2; jj++) {
                uint32_t a = sB + (uint32_t)((wn + 16 * jj + b_lrow) * PADH
                                             + b_lcol + kc * 16) * 2;
                LDMATRIX_X4(bf[jj][0], bf[jj][1], bf[jj][2], bf[jj][3], a);
            }
            #pragma unroll
            for (int i = 0; i < 4; i++)
                #pragma unroll
                for (int jj = 0; jj < 2; jj++) {
                    MMA_F16(acc[i][2*jj][0], acc[i][2*jj][1],
                            acc[i][2*jj][2], acc[i][2*jj][3],
                            af[i][0], af[i][1], af[i][2], af[i][3],
                            bf[jj][0], bf[jj][1]);
                    MMA_F16(acc[i][2*jj+1][0], acc[i][2*jj+1][1],
                            acc[i][2*jj+1][2], acc[i][2*jj+1][3],
                            af[i][0], af[i][1], af[i][2], af[i][3],
                            bf[jj][2], bf[jj][3]);
                }
        }

        if (kt + 2 < KT) issue((kt + 2) % 3, kt + 2);
        CP_COMMIT();
    }

    // ---- epilogue ----
    #pragma unroll
    for (int i = 0; i < 4; i++) {
        int r0 = bm + wm + 16 * i + lg;
        #pragma unroll
        for (int j = 0; j < 4; j++) {
            int c0 = bn + wn + 8 * j + 2 * lr;
            float2 v0 = { acc[i][j][0], acc[i][j][1] };
            float2 v1 = { acc[i][j][2], acc[i][j][3] };
            if constexpr (EPI == 1) {
                float b0 = bias[c0], b1 = bias[c0 + 1];
                v0.x = softplusf(v0.x + b0); v0.y = softplusf(v0.y + b1);
                v1.x = softplusf(v1.x + b0); v1.y = softplusf(v1.y + b1);
            } else if constexpr (EPI == 2) {
                float2 ra = *(const float2*)(resid + (size_t)r0 * NTOT + c0);
                float2 rb = *(const float2*)(resid + (size_t)(r0 + 8) * NTOT + c0);
                v0.x += ra.x; v0.y += ra.y;
                v1.x += rb.x; v1.y += rb.y;
            }
            *(float2*)(C + (size_t)r0 * NTOT + c0) = v0;
            *(float2*)(C + (size_t)(r0 + 8) * NTOT + c0) = v1;
        }
    }
}

// ---------------------------------------------------------------------------
// Depthwise causal conv1d + bias + SiLU. Writes fp32 u and fp16 copy.
// ---------------------------------------------------------------------------
__global__ void conv_silu_kernel(const float* __restrict__ wconv,
                                 const float* __restrict__ bconv)
{
    size_t idx = (size_t)blockIdx.x * blockDim.x + threadIdx.x;
    if (idx >= (size_t)ROWS * DIN) return;
    int d = (int)(idx & (DIN - 1));
    size_t row = idx >> 11;
    int l = (int)(row & (L - 1));

    float w0 = wconv[d * 4 + 0], w1 = wconv[d * 4 + 1];
    float w2 = wconv[d * 4 + 2], w3 = wconv[d * 4 + 3];
    const float* base = g_xz + row * (size_t)(2 * DIN) + d;

    float s = bconv[d];
    s = fmaf(base[0], w3, s);
    if (l >= 1) s = fmaf(*(base - 1 * 2 * DIN), w2, s);
    if (l >= 2) s = fmaf(*(base - 2 * 2 * DIN), w1, s);
    if (l >= 3) s = fmaf(*(base - 3 * 2 * DIN), w0, s);

    float sig = 1.f / (1.f + __expf(-s));
    float u = s * sig;
    g_u[idx] = u;
    g_uh[idx] = __float2half_rn(u);
}

// ---------------------------------------------------------------------------
// Bseq / Cseq (fp32, exact)
// ---------------------------------------------------------------------------
__global__ __launch_bounds__(256)
void bc_kernel(const float* __restrict__ wb, const float* __restrict__ wc)
{
    __shared__ float us[16][136];
    __shared__ float ws[128][32];

    int tid = threadIdx.x;
    int row0 = blockIdx.x * 16;
    int trow = tid >> 4;
    int tn   = (tid & 15) * 2;
    int ur = tid >> 4;
    int uc = (tid & 15) * 8;

    float a0 = 0.f, a1 = 0.f;

    for (int kb = 0; kb < DIN; kb += 128) {
        const float* up = g_u + (size_t)(row0 + ur) * DIN + kb + uc;
        *(float4*)&us[ur][uc]     = *(const float4*)(up);
        *(float4*)&us[ur][uc + 4] = *(const float4*)(up + 4);

        #pragma unroll
        for (int q = 0; q < 4; q++) {
            int fi = tid * 4 + q;
            int kk = fi >> 3;
            int part = fi & 7;
            const float* src = (part < 4)
                ? (wb + (size_t)(kb + kk) * NST + part * 4)
                : (wc + (size_t)(kb + kk) * NST + (part - 4) * 4);
            int col = (part < 4) ? part * 4 : 16 + (part - 4) * 4;
            *(float4*)&ws[kk][col] = *(const float4*)src;
        }
        __syncthreads();

        #pragma unroll 8
        for (int k = 0; k < 128; k++) {
            float uv = us[trow][k];
            float2 w2 = *(const float2*)&ws[k][tn];
            a0 = fmaf(uv, w2.x, a0);
            a1 = fmaf(uv, w2.y, a1);
        }
        __syncthreads();
    }

    int r = row0 + trow;
    if (tn < 16) {
        g_Bseq[(size_t)r * NST + tn]     = a0;
        g_Bseq[(size_t)r * NST + tn + 1] = a1;
    } else {
        g_Cseq[(size_t)r * NST + tn - 16] = a0;
        g_Cseq[(size_t)r * NST + tn - 15] = a1;
    }
}

// ---------------------------------------------------------------------------
// Chunked selective scan (pass2 writes fp16 gate)
// ---------------------------------------------------------------------------
template<bool PASS2>
__global__ void scan_kernel(const float* __restrict__ A_log,
                            const float* __restrict__ D_param)
{
    int gid = blockIdx.x * blockDim.x + threadIdx.x;
    if (gid >= BSZ * DIN * NCH) return;
    int d = gid & (DIN - 1);
    int c = (gid >> 11) & (NCH - 1);
    int b = gid >> 15;

    float A[NST];
    #pragma unroll
    for (int n = 0; n < NST; n++) A[n] = -__expf(A_log[d * NST + n]);

    bool structured = true;
    #pragma unroll
    for (int n = 1; n < NST; n++) {
        float t = (float)(n + 1) * A[0];
        if (fabsf(A[n] - t) > 1e-4f * fabsf(t)) structured = false;
    }

    float h[NST], P[NST];
    #pragma unroll
    for (int n = 0; n < NST; n++) { h[n] = 0.f; P[n] = 1.f; }

    size_t sidx = ((size_t)((b * DIN + d) * NCH + c)) * NST;
    if constexpr (PASS2) {
        #pragma unroll
        for (int n = 0; n < NST; n += 4) {
            float4 v = *(const float4*)(g_H0 + sidx + n);
            h[n] = v.x; h[n+1] = v.y; h[n+2] = v.z; h[n+3] = v.w;
        }
    }
    float Dp = PASS2 ? D_param[d] : 0.f;

    size_t row0 = (size_t)b * L + (size_t)c * LC;
    for (int t = 0; t < LC; t++) {
        size_t row = row0 + t;
        float dl = g_delta[row * DIN + d];
        float uv = g_u[row * DIN + d];
        float du = dl * uv;

        float Bv[NST];
        #pragma unroll
        for (int n = 0; n < NST; n += 4) {
            float4 v = *(const float4*)(g_Bseq + row * NST + n);
            Bv[n] = v.x; Bv[n+1] = v.y; Bv[n+2] = v.z; Bv[n+3] = v.w;
        }

        float e[NST];
        if (structured) {
            float e1 = __expf(dl * A[0]);
            float e2 = e1 * e1, e4 = e2 * e2, e8 = e4 * e4;
            e[0]  = e1;           e[1]  = e2;           e[2]  = e2 * e1;
            e[3]  = e4;           e[4]  = e4 * e1;      e[5]  = e4 * e2;
            e[6]  = e4 * e2 * e1; e[7]  = e8;           e[8]  = e8 * e1;
            e[9]  = e8 * e2;      e[10] = e8 * e2 * e1; e[11] = e8 * e4;
            e[12] = e8 * e4 * e1; e[13] = e8 * e4 * e2; e[14] = e8 * e4 * e2 * e1;
            e[15] = e8 * e8;
        } else {
            #pragma unroll
            for (int n = 0; n < NST; n++) e[n] = __expf(dl * A[n]);
        }

        #pragma unroll
        for (int n = 0; n < NST; n++) {
            h[n] = fmaf(e[n], h[n], du * Bv[n]);
            if constexpr (!PASS2) P[n] *= e[n];
        }

        if constexpr (PASS2) {
            float Cv[NST];
            #pragma unroll
            for (int n = 0; n < NST; n += 4) {
                float4 v = *(const float4*)(g_Cseq + row * NST + n);
                Cv[n] = v.x; Cv[n+1] = v.y; Cv[n+2] = v.z; Cv[n+3] = v.w;
            }
            float y = Dp * uv;
            #pragma unroll
            for (int n = 0; n < NST; n++) y = fmaf(h[n], Cv[n], y);

            float z = g_xz[row * (size_t)(2 * DIN) + DIN + d];
            float sz = z / (1.f + __expf(-z));
            g_gateh[row * DIN + d] = __float2half_rn(y * sz);
        }
    }

    if constexpr (!PASS2) {
        #pragma unroll
        for (int n = 0; n < NST; n += 4) {
            float4 vp = { P[n], P[n+1], P[n+2], P[n+3] };
            float4 vh = { h[n], h[n+1], h[n+2], h[n+3] };
            *(float4*)(g_P + sidx + n)    = vp;
            *(float4*)(g_hloc + sidx + n) = vh;
        }
    }
}

__global__ void scan_combine_kernel()
{
    int gid = blockIdx.x * blockDim.x + threadIdx.x;
    if (gid >= BSZ * DIN) return;
    size_t base = (size_t)gid * NCH * NST;
    float H[NST];
    #pragma unroll
    for (int n = 0; n < NST; n++) H[n] = 0.f;
    for (int c = 0; c < NCH; c++) {
        size_t idx = base + (size_t)c * NST;
        #pragma unroll
        for (int n = 0; n < NST; n += 4) {
            float4 v = { H[n], H[n+1], H[n+2], H[n+3] };
            *(float4*)(g_H0 + idx + n) = v;
        }
        #pragma unroll
        for (int n = 0; n < NST; n++)
            H[n] = fmaf(g_P[idx + n], H[n], g_hloc[idx + n]);
    }
}

// ---------------------------------------------------------------------------
// Launch
// ---------------------------------------------------------------------------
extern "C" void kernel_launch(void* const* d_in, const int* in_sizes, int n_in,
                              void* d_out, int out_size)
{
    const float* x       = (const float*)d_in[0];
    const float* w_norm  = (const float*)d_in[1];
    const float* b_norm  = (const float*)d_in[2];
    const float* w_in    = (const float*)d_in[3];
    const float* w_conv  = (const float*)d_in[4];
    const float* b_conv  = (const float*)d_in[5];
    const float* A_log   = (const float*)d_in[6];
    const float* w_b     = (const float*)d_in[7];
    const float* w_c     = (const float*)d_in[8];
    const float* w_delta = (const float*)d_in[9];
    const float* b_delta = (const float*)d_in[10];
    const float* D_param = (const float*)d_in[11];
    const float* w_out   = (const float*)d_in[12];
    float* out = (float*)d_out;

    cudaFuncSetAttribute(tc_gemm<2 * DIN, DM, 0, 0, 0>,
                         cudaFuncAttributeMaxDynamicSharedMemorySize, GEMM_DSMEM);
    cudaFuncSetAttribute(tc_gemm<DIN, DIN, 1, 1, 1>,
                         cudaFuncAttributeMaxDynamicSharedMemorySize, GEMM_DSMEM);
    cudaFuncSetAttribute(tc_gemm<DM, DIN, 2, 2, 2>,
                         cudaFuncAttributeMaxDynamicSharedMemorySize, GEMM_DSMEM);

    __half *wt_in, *wt_d, *wt_o;
    cudaGetSymbolAddress((void**)&wt_in, g_wtin);
    cudaGetSymbolAddress((void**)&wt_d,  g_wtd);
    cudaGetSymbolAddress((void**)&wt_o,  g_wto);

    // 0. weight transposes (+ fp16 rounding)
    transpose_h_kernel<<<dim3((2 * DIN) / 32, DM / 32), dim3(32, 8)>>>(w_in, wt_in, DM, 2 * DIN);
    transpose_h_kernel<<<dim3(DIN / 32, DIN / 32), dim3(32, 8)>>>(w_delta, wt_d, DIN, DIN);
    transpose_h_kernel<<<dim3(DM / 32, DIN / 32), dim3(32, 8)>>>(w_out, wt_o, DIN, DM);

    // 1. LayerNorm (fp16 out)
    ln_kernel<<<ROWS, 256>>>(x, w_norm, b_norm);

    // 2. xz = xn @ w_in
    tc_gemm<2 * DIN, DM, 0, 0, 0>
        <<<dim3((2 * DIN) / 128, ROWS / 128), 256, GEMM_DSMEM>>>(wt_in, nullptr, nullptr, nullptr);

    // 3. conv + silu -> u (fp32 + fp16 copy)
    conv_silu_kernel<<<(int)(((size_t)ROWS * DIN + 255) / 256), 256>>>(w_conv, b_conv);

    // 4a. Bseq/Cseq (fp32 exact)
    bc_kernel<<<ROWS / 16, 256>>>(w_b, w_c);

    // 4b. delta = softplus(u @ w_delta + b_delta)
    tc_gemm<DIN, DIN, 1, 1, 1>
        <<<dim3(DIN / 128, ROWS / 128), 256, GEMM_DSMEM>>>(wt_d, b_delta, nullptr, nullptr);

    // 5. chunked selective scan
    scan_kernel<false><<<(BSZ * DIN * NCH) / 256, 256>>>(A_log, D_param);
    scan_combine_kernel<<<(BSZ * DIN) / 256, 256>>>();
    scan_kernel<true><<<(BSZ * DIN * NCH) / 256, 256>>>(A_log, D_param);

    // 6. out = gate @ w_out + residual
    tc_gemm<DM, DIN, 2, 2, 2>
        <<<dim3(DM / 128, ROWS / 128), 256, GEMM_DSMEM>>>(wt_o, nullptr, x, out);
}

// round 7
// speedup vs baseline: 3.7690x; 1.0978x over previous
#include <cuda_runtime.h>
#include <cuda_fp16.h>
#include <cstdint>

// ---------------------------------------------------------------------------
// Problem constants
// ---------------------------------------------------------------------------
constexpr int BSZ = 2;
constexpr int L   = 2048;
constexpr int DM  = 1024;
constexpr int DIN = 2048;
constexpr int NST = 16;
constexpr int ROWS = BSZ * L;    // 4096
constexpr int NCH  = 16;
constexpr int LC   = L / NCH;    // 128
constexpr int N2   = 2176;       // combined delta|B|C|pad GEMM width (17*128)

// ---------------------------------------------------------------------------
// Scratch (static device globals)
// ---------------------------------------------------------------------------
__device__ __half g_xnh [(size_t)ROWS * DM];        // fp16 layernorm out
__device__ float  g_xz  [(size_t)ROWS * 2 * DIN];
__device__ float  g_u   [(size_t)ROWS * DIN];       // fp32 (scan)
__device__ __half g_uh  [(size_t)ROWS * DIN];       // fp16 copy (GEMM2 A)
__device__ float  g_delta[(size_t)ROWS * DIN];
__device__ float  g_Bseq [(size_t)ROWS * NST];
__device__ float  g_Cseq [(size_t)ROWS * NST];
__device__ __half g_gateh[(size_t)ROWS * DIN];      // fp16 gate (GEMM3 A)
__device__ float  g_P    [(size_t)BSZ * DIN * NCH * NST];
__device__ float  g_hloc [(size_t)BSZ * DIN * NCH * NST];
__device__ float  g_H0   [(size_t)BSZ * DIN * NCH * NST];
// transposed fp16 weights ([N][K])
__device__ __half g_wtin [(size_t)(2 * DIN) * DM];
__device__ __half g_wtd2 [(size_t)N2 * DIN];        // [wdelta^T | wb^T | wc^T | 0]
__device__ __half g_wto  [(size_t)DM * DIN];

// ---------------------------------------------------------------------------
// Helpers
// ---------------------------------------------------------------------------
__device__ __forceinline__ uint32_t smem_u32(const void* p)
{
    uint32_t a;
    asm("{ .reg .u64 t; cvta.to.shared.u64 t, %1; cvt.u32.u64 %0, t; }"
        : "=r"(a) : "l"(p));
    return a;
}

__device__ __forceinline__ float softplusf(float v)
{
    return v > 20.f ? v : log1pf(expf(v));
}

#define CP_ASYNC16(dst, src) \
    asm volatile("cp.async.cg.shared.global [%0], [%1], 16;" \
                 :: "r"(dst), "l"(src) : "memory")
#define CP_COMMIT() asm volatile("cp.async.commit_group;" ::: "memory")
#define CP_WAIT1()  asm volatile("cp.async.wait_group 1;" ::: "memory")

#define LDMATRIX_X4(r0, r1, r2, r3, addr) \
    asm volatile("ldmatrix.sync.aligned.m8n8.x4.shared.b16 {%0,%1,%2,%3}, [%4];" \
                 : "=r"(r0), "=r"(r1), "=r"(r2), "=r"(r3) : "r"(addr))

#define MMA_F16(c0, c1, c2, c3, a0, a1, a2, a3, b0, b1) \
    asm volatile("mma.sync.aligned.m16n8k16.row.col.f32.f16.f16.f32 " \
                 "{%0,%1,%2,%3}, {%4,%5,%6,%7}, {%8,%9}, {%0,%1,%2,%3};" \
                 : "+f"(c0), "+f"(c1), "+f"(c2), "+f"(c3) \
                 : "r"(a0), "r"(a1), "r"(a2), "r"(a3), "r"(b0), "r"(b1))

// ---------------------------------------------------------------------------
// LayerNorm: one block per row; fp16 output
// ---------------------------------------------------------------------------
__global__ void ln_kernel(const float* __restrict__ x,
                          const float* __restrict__ w,
                          const float* __restrict__ b)
{
    __shared__ float sh[8];
    int row = blockIdx.x;
    const float* xr = x + (size_t)row * DM;
    int i0 = threadIdx.x * 4;
    float4 v = *(const float4*)(xr + i0);
    int lane = threadIdx.x & 31, wid = threadIdx.x >> 5;

    float s = v.x + v.y + v.z + v.w;
    #pragma unroll
    for (int o = 16; o > 0; o >>= 1) s += __shfl_down_sync(0xffffffffu, s, o);
    if (lane == 0) sh[wid] = s;
    __syncthreads();
    float t = (threadIdx.x < 8) ? sh[threadIdx.x] : 0.f;
    if (wid == 0) {
        #pragma unroll
        for (int o = 4; o > 0; o >>= 1) t += __shfl_down_sync(0xffffffffu, t, o);
        if (lane == 0) sh[0] = t;
    }
    __syncthreads();
    float mu = sh[0] * (1.f / DM);
    __syncthreads();

    float d0 = v.x - mu, d1 = v.y - mu, d2 = v.z - mu, d3 = v.w - mu;
    float ss = d0*d0 + d1*d1 + d2*d2 + d3*d3;
    #pragma unroll
    for (int o = 16; o > 0; o >>= 1) ss += __shfl_down_sync(0xffffffffu, ss, o);
    if (lane == 0) sh[wid] = ss;
    __syncthreads();
    t = (threadIdx.x < 8) ? sh[threadIdx.x] : 0.f;
    if (wid == 0) {
        #pragma unroll
        for (int o = 4; o > 0; o >>= 1) t += __shfl_down_sync(0xffffffffu, t, o);
        if (lane == 0) sh[0] = t;
    }
    __syncthreads();
    float rstd = rsqrtf(sh[0] * (1.f / DM) + 1e-5f);

    float4 wv = *(const float4*)(w + i0);
    float4 bv = *(const float4*)(b + i0);
    __half2 h0 = __floats2half2_rn(d0 * rstd * wv.x + bv.x, d1 * rstd * wv.y + bv.y);
    __half2 h1 = __floats2half2_rn(d2 * rstd * wv.z + bv.z, d3 * rstd * wv.w + bv.w);
    uint2 o2 = { *(uint32_t*)&h0, *(uint32_t*)&h1 };
    *(uint2*)(g_xnh + (size_t)row * DM + i0) = o2;
}

// ---------------------------------------------------------------------------
// Weight transpose + fp16 round: out[c][r] = half(in[r][c]); in is [R][Cn]
// ---------------------------------------------------------------------------
__global__ void transpose_h_kernel(const float* __restrict__ in,
                                   __half* __restrict__ out, int R, int Cn)
{
    __shared__ float tile[32][33];
    int c0 = blockIdx.x * 32, r0 = blockIdx.y * 32;
    #pragma unroll
    for (int i = 0; i < 4; i++)
        tile[threadIdx.y + 8 * i][threadIdx.x] =
            in[(size_t)(r0 + threadIdx.y + 8 * i) * Cn + c0 + threadIdx.x];
    __syncthreads();
    #pragma unroll
    for (int i = 0; i < 4; i++) {
        float v = tile[threadIdx.x][threadIdx.y + 8 * i];
        out[(size_t)(c0 + threadIdx.y + 8 * i) * R + r0 + threadIdx.x] =
            __float2half_rn(v);
    }
}

// Append wb^T, wc^T rows and zero padding into g_wtd2 (rows 2048..2175)
__global__ void prep_wbc_kernel(const float* __restrict__ wb,
                                const float* __restrict__ wc)
{
    int k = blockIdx.x * 256 + threadIdx.x;   // 0..2047
    #pragma unroll
    for (int n = 0; n < NST; n++) {
        g_wtd2[(size_t)(2048 + n) * DIN + k] = __float2half_rn(wb[(size_t)k * NST + n]);
        g_wtd2[(size_t)(2064 + n) * DIN + k] = __float2half_rn(wc[(size_t)k * NST + n]);
    }
    for (int n = 2080; n < N2; n++)
        g_wtd2[(size_t)n * DIN + k] = __float2half_rn(0.f);
}

// ---------------------------------------------------------------------------
// FP16 mma.sync GEMM: 128 threads, 4 warps, warp tile 64x64, BM=BN=128, BK=32,
// 3-stage cp.async. EPI: 0 none, 1 bias+softplus, 2 +residual,
// 3 combined delta|Bseq|Cseq routing (GEMM2).
// ---------------------------------------------------------------------------
constexpr int PADH   = 40;                        // smem row stride (halves)
constexpr int STG_H  = 2 * 128 * PADH;            // halves per stage (A+B)
constexpr int GEMM_DSMEM = 3 * STG_H * 2;         // 61440 bytes

template<int NTOT, int K, int EPI, int ASEL>
__global__ __launch_bounds__(128, 2)
void tc_gemm(const __half* __restrict__ Bt,
             const float* __restrict__ bias,
             const float* __restrict__ resid,
             float* __restrict__ Cext)
{
    const __half* A = (ASEL == 0) ? g_xnh : (ASEL == 1) ? g_uh : g_gateh;
    float* C = (EPI == 0) ? g_xz : (EPI == 1) ? g_delta : Cext;

    extern __shared__ __half dsm[];
    uint32_t smem0 = smem_u32(dsm);

    int tid = threadIdx.x;
    int lane = tid & 31, wid = tid >> 5;
    int wm = (wid & 1) * 64;
    int wn = (wid >> 1) * 64;
    int bm = blockIdx.y * 128;
    int bn = blockIdx.x * 128;
    int lr = lane & 3;
    int lg = lane >> 2;

    const __half* Ag0 = A  + (size_t)bm * K;
    const __half* Bg0 = Bt + (size_t)bn * K;

    int ld_row = tid >> 2;            // 0..31
    int ld_c16 = (tid & 3) * 16;      // byte offset in 64B row

    int a_lrow = ((lane >> 3) & 1) * 8 + (lane & 7);
    int a_lcol = (lane >> 4) * 8;
    int b_lrow = (lane >> 4) * 8 + (lane & 7);
    int b_lcol = ((lane >> 3) & 1) * 8;

    constexpr int KT = K / 32;

    auto issue = [&](int stage, int kt) {
        uint32_t sA = smem0 + (uint32_t)stage * STG_H * 2;
        uint32_t sB = sA + 128 * PADH * 2;
        const __half* Ag = Ag0 + kt * 32;
        const __half* Bg = Bg0 + kt * 32;
        #pragma unroll
        for (int q = 0; q < 4; q++) {
            int r = q * 32 + ld_row;
            CP_ASYNC16(sA + (uint32_t)(r * PADH * 2) + ld_c16,
                       (const char*)(Ag + (size_t)r * K) + ld_c16);
            CP_ASYNC16(sB + (uint32_t)(r * PADH * 2) + ld_c16,
                       (const char*)(Bg + (size_t)r * K) + ld_c16);
        }
    };

    float acc[4][8][4];
    #pragma unroll
    for (int i = 0; i < 4; i++)
        #pragma unroll
        for (int j = 0; j < 8; j++)
            #pragma unroll
            for (int q = 0; q < 4; q++) acc[i][j][q] = 0.f;

    issue(0, 0); CP_COMMIT();
    issue(1, 1); CP_COMMIT();

    for (int kt = 0; kt < KT; kt++) {
        CP_WAIT1();
        __syncthreads();

        uint32_t sA = smem0 + (uint32_t)(kt % 3) * STG_H * 2;
        uint32_t sB = sA + 128 * PADH * 2;

        #pragma unroll
        for (int kc = 0; kc < 2; kc++) {
            uint32_t af[4][4], bf[4][4];
            #pragma unroll
            for (int i = 0; i < 4; i++) {
                uint32_t a = sA + (uint32_t)((wm + 16 * i + a_lrow) * PADH
                                             + a_lcol + kc * 16) * 2;
                LDMATRIX_X4(af[i][0], af[i][1], af[i][2], af[i][3], a);
            }
            #pragma unroll
            for (int jj = 0; jj < 4; jj++) {
                uint32_t a = sB + (uint32_t)((wn + 16 * jj + b_lrow) * PADH
                                             + b_lcol + kc * 16) * 2;
                LDMATRIX_X4(bf[jj][0], bf[jj][1], bf[jj][2], bf[jj][3], a);
            }
            #pragma unroll
            for (int i = 0; i < 4; i++)
                #pragma unroll
                for (int jj = 0; jj < 4; jj++) {
                    MMA_F16(acc[i][2*jj][0], acc[i][2*jj][1],
                            acc[i][2*jj][2], acc[i][2*jj][3],
                            af[i][0], af[i][1], af[i][2], af[i][3],
                            bf[jj][0], bf[jj][1]);
                    MMA_F16(acc[i][2*jj+1][0], acc[i][2*jj+1][1],
                            acc[i][2*jj+1][2], acc[i][2*jj+1][3],
                            af[i][0], af[i][1], af[i][2], af[i][3],
                            bf[jj][2], bf[jj][3]);
                }
        }

        if (kt + 2 < KT) issue((kt + 2) % 3, kt + 2);
        CP_COMMIT();
    }

    // ---- epilogue ----
    #pragma unroll
    for (int i = 0; i < 4; i++) {
        int r0 = bm + wm + 16 * i + lg;
        #pragma unroll
        for (int j = 0; j < 8; j++) {
            int c0 = bn + wn + 8 * j + 2 * lr;
            float2 v0 = { acc[i][j][0], acc[i][j][1] };   // row r0
            float2 v1 = { acc[i][j][2], acc[i][j][3] };   // row r0+8
            if constexpr (EPI == 3) {
                if (c0 < DIN) {
                    float b0 = bias[c0], b1 = bias[c0 + 1];
                    v0.x = softplusf(v0.x + b0); v0.y = softplusf(v0.y + b1);
                    v1.x = softplusf(v1.x + b0); v1.y = softplusf(v1.y + b1);
                    *(float2*)(g_delta + (size_t)r0 * DIN + c0) = v0;
                    *(float2*)(g_delta + (size_t)(r0 + 8) * DIN + c0) = v1;
                } else if (c0 < DIN + NST) {
                    int n = c0 - DIN;
                    *(float2*)(g_Bseq + (size_t)r0 * NST + n) = v0;
                    *(float2*)(g_Bseq + (size_t)(r0 + 8) * NST + n) = v1;
                } else if (c0 < DIN + 2 * NST) {
                    int n = c0 - DIN - NST;
                    *(float2*)(g_Cseq + (size_t)r0 * NST + n) = v0;
                    *(float2*)(g_Cseq + (size_t)(r0 + 8) * NST + n) = v1;
                }
            } else {
                if constexpr (EPI == 2) {
                    float2 ra = *(const float2*)(resid + (size_t)r0 * NTOT + c0);
                    float2 rb = *(const float2*)(resid + (size_t)(r0 + 8) * NTOT + c0);
                    v0.x += ra.x; v0.y += ra.y;
                    v1.x += rb.x; v1.y += rb.y;
                }
                *(float2*)(C + (size_t)r0 * NTOT + c0) = v0;
                *(float2*)(C + (size_t)(r0 + 8) * NTOT + c0) = v1;
            }
        }
    }
}

// ---------------------------------------------------------------------------
// Depthwise causal conv1d + bias + SiLU. Writes fp32 u and fp16 copy.
// ---------------------------------------------------------------------------
__global__ void conv_silu_kernel(const float* __restrict__ wconv,
                                 const float* __restrict__ bconv)
{
    size_t idx = (size_t)blockIdx.x * blockDim.x + threadIdx.x;
    if (idx >= (size_t)ROWS * DIN) return;
    int d = (int)(idx & (DIN - 1));
    size_t row = idx >> 11;
    int l = (int)(row & (L - 1));

    float w0 = wconv[d * 4 + 0], w1 = wconv[d * 4 + 1];
    float w2 = wconv[d * 4 + 2], w3 = wconv[d * 4 + 3];
    const float* base = g_xz + row * (size_t)(2 * DIN) + d;

    float s = bconv[d];
    s = fmaf(base[0], w3, s);
    if (l >= 1) s = fmaf(*(base - 1 * 2 * DIN), w2, s);
    if (l >= 2) s = fmaf(*(base - 2 * 2 * DIN), w1, s);
    if (l >= 3) s = fmaf(*(base - 3 * 2 * DIN), w0, s);

    float sig = 1.f / (1.f + __expf(-s));
    float u = s * sig;
    g_u[idx] = u;
    g_uh[idx] = __float2half_rn(u);
}

// ---------------------------------------------------------------------------
// Chunked selective scan (pass2 writes fp16 gate)
// ---------------------------------------------------------------------------
template<bool PASS2>
__global__ void scan_kernel(const float* __restrict__ A_log,
                            const float* __restrict__ D_param)
{
    int gid = blockIdx.x * blockDim.x + threadIdx.x;
    if (gid >= BSZ * DIN * NCH) return;
    int d = gid & (DIN - 1);
    int c = (gid >> 11) & (NCH - 1);
    int b = gid >> 15;

    float A[NST];
    #pragma unroll
    for (int n = 0; n < NST; n++) A[n] = -__expf(A_log[d * NST + n]);

    bool structured = true;
    #pragma unroll
    for (int n = 1; n < NST; n++) {
        float t = (float)(n + 1) * A[0];
        if (fabsf(A[n] - t) > 1e-4f * fabsf(t)) structured = false;
    }

    float h[NST], P[NST];
    #pragma unroll
    for (int n = 0; n < NST; n++) { h[n] = 0.f; P[n] = 1.f; }

    size_t sidx = ((size_t)((b * DIN + d) * NCH + c)) * NST;
    if constexpr (PASS2) {
        #pragma unroll
        for (int n = 0; n < NST; n += 4) {
            float4 v = *(const float4*)(g_H0 + sidx + n);
            h[n] = v.x; h[n+1] = v.y; h[n+2] = v.z; h[n+3] = v.w;
        }
    }
    float Dp = PASS2 ? D_param[d] : 0.f;

    size_t row0 = (size_t)b * L + (size_t)c * LC;
    for (int t = 0; t < LC; t++) {
        size_t row = row0 + t;
        float dl = g_delta[row * DIN + d];
        float uv = g_u[row * DIN + d];
        float du = dl * uv;

        float Bv[NST];
        #pragma unroll
        for (int n = 0; n < NST; n += 4) {
            float4 v = *(const float4*)(g_Bseq + row * NST + n);
            Bv[n] = v.x; Bv[n+1] = v.y; Bv[n+2] = v.z; Bv[n+3] = v.w;
        }

        float e[NST];
        if (structured) {
            float e1 = __expf(dl * A[0]);
            float e2 = e1 * e1, e4 = e2 * e2, e8 = e4 * e4;
            e[0]  = e1;           e[1]  = e2;           e[2]  = e2 * e1;
            e[3]  = e4;           e[4]  = e4 * e1;      e[5]  = e4 * e2;
            e[6]  = e4 * e2 * e1; e[7]  = e8;           e[8]  = e8 * e1;
            e[9]  = e8 * e2;      e[10] = e8 * e2 * e1; e[11] = e8 * e4;
            e[12] = e8 * e4 * e1; e[13] = e8 * e4 * e2; e[14] = e8 * e4 * e2 * e1;
            e[15] = e8 * e8;
        } else {
            #pragma unroll
            for (int n = 0; n < NST; n++) e[n] = __expf(dl * A[n]);
        }

        #pragma unroll
        for (int n = 0; n < NST; n++) {
            h[n] = fmaf(e[n], h[n], du * Bv[n]);
            if constexpr (!PASS2) P[n] *= e[n];
        }

        if constexpr (PASS2) {
            float Cv[NST];
            #pragma unroll
            for (int n = 0; n < NST; n += 4) {
                float4 v = *(const float4*)(g_Cseq + row * NST + n);
                Cv[n] = v.x; Cv[n+1] = v.y; Cv[n+2] = v.z; Cv[n+3] = v.w;
            }
            float y = Dp * uv;
            #pragma unroll
            for (int n = 0; n < NST; n++) y = fmaf(h[n], Cv[n], y);

            float z = g_xz[row * (size_t)(2 * DIN) + DIN + d];
            float sz = z / (1.f + __expf(-z));
            g_gateh[row * DIN + d] = __float2half_rn(y * sz);
        }
    }

    if constexpr (!PASS2) {
        #pragma unroll
        for (int n = 0; n < NST; n += 4) {
            float4 vp = { P[n], P[n+1], P[n+2], P[n+3] };
            float4 vh = { h[n], h[n+1], h[n+2], h[n+3] };
            *(float4*)(g_P + sidx + n)    = vp;
            *(float4*)(g_hloc + sidx + n) = vh;
        }
    }
}

__global__ void scan_combine_kernel()
{
    int gid = blockIdx.x * blockDim.x + threadIdx.x;
    if (gid >= BSZ * DIN) return;
    size_t base = (size_t)gid * NCH * NST;
    float H[NST];
    #pragma unroll
    for (int n = 0; n < NST; n++) H[n] = 0.f;
    for (int c = 0; c < NCH; c++) {
        size_t idx = base + (size_t)c * NST;
        #pragma unroll
        for (int n = 0; n < NST; n += 4) {
            float4 v = { H[n], H[n+1], H[n+2], H[n+3] };
            *(float4*)(g_H0 + idx + n) = v;
        }
        #pragma unroll
        for (int n = 0; n < NST; n++)
            H[n] = fmaf(g_P[idx + n], H[n], g_hloc[idx + n]);
    }
}

// ---------------------------------------------------------------------------
// Launch
// ---------------------------------------------------------------------------
extern "C" void kernel_launch(void* const* d_in, const int* in_sizes, int n_in,
                              void* d_out, int out_size)
{
    const float* x       = (const float*)d_in[0];
    const float* w_norm  = (const float*)d_in[1];
    const float* b_norm  = (const float*)d_in[2];
    const float* w_in    = (const float*)d_in[3];
    const float* w_conv  = (const float*)d_in[4];
    const float* b_conv  = (const float*)d_in[5];
    const float* A_log   = (const float*)d_in[6];
    const float* w_b     = (const float*)d_in[7];
    const float* w_c     = (const float*)d_in[8];
    const float* w_delta = (const float*)d_in[9];
    const float* b_delta = (const float*)d_in[10];
    const float* D_param = (const float*)d_in[11];
    const float* w_out   = (const float*)d_in[12];
    float* out = (float*)d_out;

    cudaFuncSetAttribute(tc_gemm<2 * DIN, DM, 0, 0>,
                         cudaFuncAttributeMaxDynamicSharedMemorySize, GEMM_DSMEM);
    cudaFuncSetAttribute(tc_gemm<N2, DIN, 3, 1>,
                         cudaFuncAttributeMaxDynamicSharedMemorySize, GEMM_DSMEM);
    cudaFuncSetAttribute(tc_gemm<DM, DIN, 2, 2>,
                         cudaFuncAttributeMaxDynamicSharedMemorySize, GEMM_DSMEM);

    __half *wt_in, *wt_d2, *wt_o;
    cudaGetSymbolAddress((void**)&wt_in, g_wtin);
    cudaGetSymbolAddress((void**)&wt_d2, g_wtd2);
    cudaGetSymbolAddress((void**)&wt_o,  g_wto);

    // 0. weight prep: transposes (+ fp16 rounding) and combined delta|B|C
    transpose_h_kernel<<<dim3((2 * DIN) / 32, DM / 32), dim3(32, 8)>>>(w_in, wt_in, DM, 2 * DIN);
    transpose_h_kernel<<<dim3(DIN / 32, DIN / 32), dim3(32, 8)>>>(w_delta, wt_d2, DIN, DIN);
    prep_wbc_kernel<<<DIN / 256, 256>>>(w_b, w_c);
    transpose_h_kernel<<<dim3(DM / 32, DIN / 32), dim3(32, 8)>>>(w_out, wt_o, DIN, DM);

    // 1. LayerNorm (fp16 out)
    ln_kernel<<<ROWS, 256>>>(x, w_norm, b_norm);

    // 2. xz = xn @ w_in
    tc_gemm<2 * DIN, DM, 0, 0>
        <<<dim3((2 * DIN) / 128, ROWS / 128), 128, GEMM_DSMEM>>>(wt_in, nullptr, nullptr, nullptr);

    // 3. conv + silu -> u (fp32 + fp16 copy)
    conv_silu_kernel<<<(int)(((size_t)ROWS * DIN + 255) / 256), 256>>>(w_conv, b_conv);

    // 4. combined: delta = softplus(u@w_delta + b), Bseq = u@w_b, Cseq = u@w_c
    tc_gemm<N2, DIN, 3, 1>
        <<<dim3(N2 / 128, ROWS / 128), 128, GEMM_DSMEM>>>(wt_d2, b_delta, nullptr, nullptr);

    // 5. chunked selective scan
    scan_kernel<false><<<(BSZ * DIN * NCH) / 256, 256>>>(A_log, D_param);
    scan_combine_kernel<<<(BSZ * DIN) / 256, 256>>>();
    scan_kernel<true><<<(BSZ * DIN * NCH) / 256, 256>>>(A_log, D_param);

    // 6. out = gate @ w_out + residual
    tc_gemm<DM, DIN, 2, 2>
        <<<dim3(DM / 128, ROWS / 128), 128, GEMM_DSMEM>>>(wt_o, nullptr, x, out);
}

// round 8
// speedup vs baseline: 4.0665x; 1.0789x over previous
#include <cuda_runtime.h>
#include <cuda_fp16.h>
#include <cstdint>

// ---------------------------------------------------------------------------
// Problem constants
// ---------------------------------------------------------------------------
constexpr int BSZ = 2;
constexpr int L   = 2048;
constexpr int DM  = 1024;
constexpr int DIN = 2048;
constexpr int NST = 16;
constexpr int ROWS = BSZ * L;    // 4096
constexpr int NCH  = 16;
constexpr int LC   = L / NCH;    // 128
constexpr int N2   = 2176;       // combined delta|B|C|pad GEMM width (17*128)

// ---------------------------------------------------------------------------
// Scratch (static device globals)
// ---------------------------------------------------------------------------
__device__ __half g_xnh [(size_t)ROWS * DM];        // fp16 layernorm out
__device__ __half g_xzh [(size_t)ROWS * 2 * DIN];   // fp16 in-proj out (x|z)
__device__ __half g_uh  [(size_t)ROWS * DIN];       // fp16 conv+silu out
__device__ float  g_delta[(size_t)ROWS * DIN];
__device__ float  g_Bseq [(size_t)ROWS * NST];
__device__ float  g_Cseq [(size_t)ROWS * NST];
__device__ __half g_gateh[(size_t)ROWS * DIN];      // fp16 gate (GEMM3 A)
__device__ float  g_P    [(size_t)BSZ * DIN * NCH * NST];
__device__ float  g_hloc [(size_t)BSZ * DIN * NCH * NST];
__device__ float  g_H0   [(size_t)BSZ * DIN * NCH * NST];
// transposed fp16 weights ([N][K])
__device__ __half g_wtin [(size_t)(2 * DIN) * DM];
__device__ __half g_wtd2 [(size_t)N2 * DIN];        // [wdelta^T | wb^T | wc^T | 0]
__device__ __half g_wto  [(size_t)DM * DIN];

// ---------------------------------------------------------------------------
// Helpers
// ---------------------------------------------------------------------------
__device__ __forceinline__ uint32_t smem_u32(const void* p)
{
    uint32_t a;
    asm("{ .reg .u64 t; cvta.to.shared.u64 t, %1; cvt.u32.u64 %0, t; }"
        : "=r"(a) : "l"(p));
    return a;
}

__device__ __forceinline__ float softplusf(float v)
{
    return v > 20.f ? v : log1pf(expf(v));
}

#define CP_ASYNC16(dst, src) \
    asm volatile("cp.async.cg.shared.global [%0], [%1], 16;" \
                 :: "r"(dst), "l"(src) : "memory")
#define CP_COMMIT() asm volatile("cp.async.commit_group;" ::: "memory")
#define CP_WAIT2()  asm volatile("cp.async.wait_group 2;" ::: "memory")

#define LDMATRIX_X4(r0, r1, r2, r3, addr) \
    asm volatile("ldmatrix.sync.aligned.m8n8.x4.shared.b16 {%0,%1,%2,%3}, [%4];" \
                 : "=r"(r0), "=r"(r1), "=r"(r2), "=r"(r3) : "r"(addr))

#define MMA_F16(c0, c1, c2, c3, a0, a1, a2, a3, b0, b1) \
    asm volatile("mma.sync.aligned.m16n8k16.row.col.f32.f16.f16.f32 " \
                 "{%0,%1,%2,%3}, {%4,%5,%6,%7}, {%8,%9}, {%0,%1,%2,%3};" \
                 : "+f"(c0), "+f"(c1), "+f"(c2), "+f"(c3) \
                 : "r"(a0), "r"(a1), "r"(a2), "r"(a3), "r"(b0), "r"(b1))

// ---------------------------------------------------------------------------
// LayerNorm: one block per row; fp16 output
// ---------------------------------------------------------------------------
__global__ void ln_kernel(const float* __restrict__ x,
                          const float* __restrict__ w,
                          const float* __restrict__ b)
{
    __shared__ float sh[8];
    int row = blockIdx.x;
    const float* xr = x + (size_t)row * DM;
    int i0 = threadIdx.x * 4;
    float4 v = *(const float4*)(xr + i0);
    int lane = threadIdx.x & 31, wid = threadIdx.x >> 5;

    float s = v.x + v.y + v.z + v.w;
    #pragma unroll
    for (int o = 16; o > 0; o >>= 1) s += __shfl_down_sync(0xffffffffu, s, o);
    if (lane == 0) sh[wid] = s;
    __syncthreads();
    float t = (threadIdx.x < 8) ? sh[threadIdx.x] : 0.f;
    if (wid == 0) {
        #pragma unroll
        for (int o = 4; o > 0; o >>= 1) t += __shfl_down_sync(0xffffffffu, t, o);
        if (lane == 0) sh[0] = t;
    }
    __syncthreads();
    float mu = sh[0] * (1.f / DM);
    __syncthreads();

    float d0 = v.x - mu, d1 = v.y - mu, d2 = v.z - mu, d3 = v.w - mu;
    float ss = d0*d0 + d1*d1 + d2*d2 + d3*d3;
    #pragma unroll
    for (int o = 16; o > 0; o >>= 1) ss += __shfl_down_sync(0xffffffffu, ss, o);
    if (lane == 0) sh[wid] = ss;
    __syncthreads();
    t = (threadIdx.x < 8) ? sh[threadIdx.x] : 0.f;
    if (wid == 0) {
        #pragma unroll
        for (int o = 4; o > 0; o >>= 1) t += __shfl_down_sync(0xffffffffu, t, o);
        if (lane == 0) sh[0] = t;
    }
    __syncthreads();
    float rstd = rsqrtf(sh[0] * (1.f / DM) + 1e-5f);

    float4 wv = *(const float4*)(w + i0);
    float4 bv = *(const float4*)(b + i0);
    __half2 h0 = __floats2half2_rn(d0 * rstd * wv.x + bv.x, d1 * rstd * wv.y + bv.y);
    __half2 h1 = __floats2half2_rn(d2 * rstd * wv.z + bv.z, d3 * rstd * wv.w + bv.w);
    uint2 o2 = { *(uint32_t*)&h0, *(uint32_t*)&h1 };
    *(uint2*)(g_xnh + (size_t)row * DM + i0) = o2;
}

// ---------------------------------------------------------------------------
// Weight transpose + fp16 round: out[c][r] = half(in[r][c]); in is [R][Cn]
// ---------------------------------------------------------------------------
__global__ void transpose_h_kernel(const float* __restrict__ in,
                                   __half* __restrict__ out, int R, int Cn)
{
    __shared__ float tile[32][33];
    int c0 = blockIdx.x * 32, r0 = blockIdx.y * 32;
    #pragma unroll
    for (int i = 0; i < 4; i++)
        tile[threadIdx.y + 8 * i][threadIdx.x] =
            in[(size_t)(r0 + threadIdx.y + 8 * i) * Cn + c0 + threadIdx.x];
    __syncthreads();
    #pragma unroll
    for (int i = 0; i < 4; i++) {
        float v = tile[threadIdx.x][threadIdx.y + 8 * i];
        out[(size_t)(c0 + threadIdx.y + 8 * i) * R + r0 + threadIdx.x] =
            __float2half_rn(v);
    }
}

// Append wb^T, wc^T rows and zero padding into g_wtd2 (rows 2048..2175)
__global__ void prep_wbc_kernel(const float* __restrict__ wb,
                                const float* __restrict__ wc)
{
    int k = blockIdx.x * 256 + threadIdx.x;   // 0..2047
    #pragma unroll
    for (int n = 0; n < NST; n++) {
        g_wtd2[(size_t)(2048 + n) * DIN + k] = __float2half_rn(wb[(size_t)k * NST + n]);
        g_wtd2[(size_t)(2064 + n) * DIN + k] = __float2half_rn(wc[(size_t)k * NST + n]);
    }
    for (int n = 2080; n < N2; n++)
        g_wtd2[(size_t)n * DIN + k] = __float2half_rn(0.f);
}

// ---------------------------------------------------------------------------
// FP16 mma.sync GEMM: 128 threads, 4 warps, warp tile 64x64, BM=BN=128, BK=32,
// 4-stage cp.async (wait_group 2). EPI: 0 fp16 out (xz), 2 +residual fp32 out,
// 3 combined delta|Bseq|Cseq routing.
// ---------------------------------------------------------------------------
constexpr int PADH   = 40;                        // smem row stride (halves)
constexpr int STG_H  = 2 * 128 * PADH;            // halves per stage (A+B)
constexpr int NSTG   = 4;
constexpr int GEMM_DSMEM = NSTG * STG_H * 2;      // 81920 bytes

template<int NTOT, int K, int EPI, int ASEL>
__global__ __launch_bounds__(128, 2)
void tc_gemm(const __half* __restrict__ Bt,
             const float* __restrict__ bias,
             const float* __restrict__ resid,
             float* __restrict__ Cext)
{
    const __half* A = (ASEL == 0) ? g_xnh : (ASEL == 1) ? g_uh : g_gateh;

    extern __shared__ __half dsm[];
    uint32_t smem0 = smem_u32(dsm);

    int tid = threadIdx.x;
    int lane = tid & 31, wid = tid >> 5;
    int wm = (wid & 1) * 64;
    int wn = (wid >> 1) * 64;
    int bm = blockIdx.y * 128;
    int bn = blockIdx.x * 128;
    int lr = lane & 3;
    int lg = lane >> 2;

    const __half* Ag0 = A  + (size_t)bm * K;
    const __half* Bg0 = Bt + (size_t)bn * K;

    int ld_row = tid >> 2;            // 0..31
    int ld_c16 = (tid & 3) * 16;      // byte offset in 64B row

    int a_lrow = ((lane >> 3) & 1) * 8 + (lane & 7);
    int a_lcol = (lane >> 4) * 8;
    int b_lrow = (lane >> 4) * 8 + (lane & 7);
    int b_lcol = ((lane >> 3) & 1) * 8;

    constexpr int KT = K / 32;

    auto issue = [&](int stage, int kt) {
        uint32_t sA = smem0 + (uint32_t)stage * STG_H * 2;
        uint32_t sB = sA + 128 * PADH * 2;
        const __half* Ag = Ag0 + kt * 32;
        const __half* Bg = Bg0 + kt * 32;
        #pragma unroll
        for (int q = 0; q < 4; q++) {
            int r = q * 32 + ld_row;
            CP_ASYNC16(sA + (uint32_t)(r * PADH * 2) + ld_c16,
                       (const char*)(Ag + (size_t)r * K) + ld_c16);
            CP_ASYNC16(sB + (uint32_t)(r * PADH * 2) + ld_c16,
                       (const char*)(Bg + (size_t)r * K) + ld_c16);
        }
    };

    float acc[4][8][4];
    #pragma unroll
    for (int i = 0; i < 4; i++)
        #pragma unroll
        for (int j = 0; j < 8; j++)
            #pragma unroll
            for (int q = 0; q < 4; q++) acc[i][j][q] = 0.f;

    issue(0, 0); CP_COMMIT();
    issue(1, 1); CP_COMMIT();
    issue(2, 2); CP_COMMIT();

    for (int kt = 0; kt < KT; kt++) {
        CP_WAIT2();
        __syncthreads();

        uint32_t sA = smem0 + (uint32_t)(kt % NSTG) * STG_H * 2;
        uint32_t sB = sA + 128 * PADH * 2;

        #pragma unroll
        for (int kc = 0; kc < 2; kc++) {
            uint32_t af[4][4], bf[4][4];
            #pragma unroll
            for (int i = 0; i < 4; i++) {
                uint32_t a = sA + (uint32_t)((wm + 16 * i + a_lrow) * PADH
                                             + a_lcol + kc * 16) * 2;
                LDMATRIX_X4(af[i][0], af[i][1], af[i][2], af[i][3], a);
            }
            #pragma unroll
            for (int jj = 0; jj < 4; jj++) {
                uint32_t a = sB + (uint32_t)((wn + 16 * jj + b_lrow) * PADH
                                             + b_lcol + kc * 16) * 2;
                LDMATRIX_X4(bf[jj][0], bf[jj][1], bf[jj][2], bf[jj][3], a);
            }
            #pragma unroll
            for (int i = 0; i < 4; i++)
                #pragma unroll
                for (int jj = 0; jj < 4; jj++) {
                    MMA_F16(acc[i][2*jj][0], acc[i][2*jj][1],
                            acc[i][2*jj][2], acc[i][2*jj][3],
                            af[i][0], af[i][1], af[i][2], af[i][3],
                            bf[jj][0], bf[jj][1]);
                    MMA_F16(acc[i][2*jj+1][0], acc[i][2*jj+1][1],
                            acc[i][2*jj+1][2], acc[i][2*jj+1][3],
                            af[i][0], af[i][1], af[i][2], af[i][3],
                            bf[jj][2], bf[jj][3]);
                }
        }

        if (kt + 3 < KT) issue((kt + 3) % NSTG, kt + 3);
        CP_COMMIT();
    }

    // ---- epilogue ----
    #pragma unroll
    for (int i = 0; i < 4; i++) {
        int r0 = bm + wm + 16 * i + lg;
        #pragma unroll
        for (int j = 0; j < 8; j++) {
            int c0 = bn + wn + 8 * j + 2 * lr;
            float2 v0 = { acc[i][j][0], acc[i][j][1] };   // row r0
            float2 v1 = { acc[i][j][2], acc[i][j][3] };   // row r0+8
            if constexpr (EPI == 0) {
                __half2 h0 = __floats2half2_rn(v0.x, v0.y);
                __half2 h1 = __floats2half2_rn(v1.x, v1.y);
                *(uint32_t*)(g_xzh + (size_t)r0 * NTOT + c0) = *(uint32_t*)&h0;
                *(uint32_t*)(g_xzh + (size_t)(r0 + 8) * NTOT + c0) = *(uint32_t*)&h1;
            } else if constexpr (EPI == 3) {
                if (c0 < DIN) {
                    float b0 = bias[c0], b1 = bias[c0 + 1];
                    v0.x = softplusf(v0.x + b0); v0.y = softplusf(v0.y + b1);
                    v1.x = softplusf(v1.x + b0); v1.y = softplusf(v1.y + b1);
                    *(float2*)(g_delta + (size_t)r0 * DIN + c0) = v0;
                    *(float2*)(g_delta + (size_t)(r0 + 8) * DIN + c0) = v1;
                } else if (c0 < DIN + NST) {
                    int n = c0 - DIN;
                    *(float2*)(g_Bseq + (size_t)r0 * NST + n) = v0;
                    *(float2*)(g_Bseq + (size_t)(r0 + 8) * NST + n) = v1;
                } else if (c0 < DIN + 2 * NST) {
                    int n = c0 - DIN - NST;
                    *(float2*)(g_Cseq + (size_t)r0 * NST + n) = v0;
                    *(float2*)(g_Cseq + (size_t)(r0 + 8) * NST + n) = v1;
                }
            } else {
                float2 ra = *(const float2*)(resid + (size_t)r0 * NTOT + c0);
                float2 rb = *(const float2*)(resid + (size_t)(r0 + 8) * NTOT + c0);
                v0.x += ra.x; v0.y += ra.y;
                v1.x += rb.x; v1.y += rb.y;
                *(float2*)(Cext + (size_t)r0 * NTOT + c0) = v0;
                *(float2*)(Cext + (size_t)(r0 + 8) * NTOT + c0) = v1;
            }
        }
    }
}

// ---------------------------------------------------------------------------
// Depthwise causal conv1d + bias + SiLU. 8 channels/thread, fp16 in/out.
// ---------------------------------------------------------------------------
__global__ void conv_silu_kernel(const float* __restrict__ wconv,
                                 const float* __restrict__ bconv)
{
    int t = blockIdx.x * blockDim.x + threadIdx.x;   // ROWS*DIN/8 threads
    int dg = t & (DIN / 8 - 1);
    int d0 = dg * 8;
    int row = t >> 8;                 // DIN/8 = 256 groups per row
    int l = row & (L - 1);

    // load up to 4 input rows of 8 halves each
    float xv[4][8];
    #pragma unroll
    for (int j = 0; j < 4; j++) {
        if (l >= j) {
            uint4 r4 = *(const uint4*)(g_xzh + (size_t)(row - j) * (2 * DIN) + d0);
            const __half2* hp = (const __half2*)&r4;
            #pragma unroll
            for (int q = 0; q < 4; q++) {
                float2 f2 = __half22float2(hp[q]);
                xv[j][2*q]   = f2.x;
                xv[j][2*q+1] = f2.y;
            }
        } else {
            #pragma unroll
            for (int q = 0; q < 8; q++) xv[j][q] = 0.f;
        }
    }

    __half hout[8];
    #pragma unroll
    for (int c = 0; c < 8; c++) {
        float4 w4 = *(const float4*)(wconv + (size_t)(d0 + c) * 4);
        float s = bconv[d0 + c];
        s = fmaf(xv[0][c], w4.w, s);      // tap 3 -> current row
        s = fmaf(xv[1][c], w4.z, s);
        s = fmaf(xv[2][c], w4.y, s);
        s = fmaf(xv[3][c], w4.x, s);
        float sig = 1.f / (1.f + __expf(-s));
        hout[c] = __float2half_rn(s * sig);
    }
    *(uint4*)(g_uh + (size_t)row * DIN + d0) = *(uint4*)hout;
}

// ---------------------------------------------------------------------------
// Chunked selective scan (fp16 u/z inputs; pass2 writes fp16 gate)
// ---------------------------------------------------------------------------
template<bool PASS2>
__global__ void scan_kernel(const float* __restrict__ A_log,
                            const float* __restrict__ D_param)
{
    int gid = blockIdx.x * blockDim.x + threadIdx.x;
    if (gid >= BSZ * DIN * NCH) return;
    int d = gid & (DIN - 1);
    int c = (gid >> 11) & (NCH - 1);
    int b = gid >> 15;

    float A[NST];
    #pragma unroll
    for (int n = 0; n < NST; n++) A[n] = -__expf(A_log[d * NST + n]);

    bool structured = true;
    #pragma unroll
    for (int n = 1; n < NST; n++) {
        float t = (float)(n + 1) * A[0];
        if (fabsf(A[n] - t) > 1e-4f * fabsf(t)) structured = false;
    }

    float h[NST], P[NST];
    #pragma unroll
    for (int n = 0; n < NST; n++) { h[n] = 0.f; P[n] = 1.f; }

    size_t sidx = ((size_t)((b * DIN + d) * NCH + c)) * NST;
    if constexpr (PASS2) {
        #pragma unroll
        for (int n = 0; n < NST; n += 4) {
            float4 v = *(const float4*)(g_H0 + sidx + n);
            h[n] = v.x; h[n+1] = v.y; h[n+2] = v.z; h[n+3] = v.w;
        }
    }
    float Dp = PASS2 ? D_param[d] : 0.f;

    size_t row0 = (size_t)b * L + (size_t)c * LC;
    for (int t = 0; t < LC; t++) {
        size_t row = row0 + t;
        float dl = g_delta[row * DIN + d];
        float uv = __half2float(g_uh[row * DIN + d]);
        float du = dl * uv;

        float Bv[NST];
        #pragma unroll
        for (int n = 0; n < NST; n += 4) {
            float4 v = *(const float4*)(g_Bseq + row * NST + n);
            Bv[n] = v.x; Bv[n+1] = v.y; Bv[n+2] = v.z; Bv[n+3] = v.w;
        }

        float e[NST];
        if (structured) {
            float e1 = __expf(dl * A[0]);
            float e2 = e1 * e1, e4 = e2 * e2, e8 = e4 * e4;
            e[0]  = e1;           e[1]  = e2;           e[2]  = e2 * e1;
            e[3]  = e4;           e[4]  = e4 * e1;      e[5]  = e4 * e2;
            e[6]  = e4 * e2 * e1; e[7]  = e8;           e[8]  = e8 * e1;
            e[9]  = e8 * e2;      e[10] = e8 * e2 * e1; e[11] = e8 * e4;
            e[12] = e8 * e4 * e1; e[13] = e8 * e4 * e2; e[14] = e8 * e4 * e2 * e1;
            e[15] = e8 * e8;
        } else {
            #pragma unroll
            for (int n = 0; n < NST; n++) e[n] = __expf(dl * A[n]);
        }

        #pragma unroll
        for (int n = 0; n < NST; n++) {
            h[n] = fmaf(e[n], h[n], du * Bv[n]);
            if constexpr (!PASS2) P[n] *= e[n];
        }

        if constexpr (PASS2) {
            float Cv[NST];
            #pragma unroll
            for (int n = 0; n < NST; n += 4) {
                float4 v = *(const float4*)(g_Cseq + row * NST + n);
                Cv[n] = v.x; Cv[n+1] = v.y; Cv[n+2] = v.z; Cv[n+3] = v.w;
            }
            float y = Dp * uv;
            #pragma unroll
            for (int n = 0; n < NST; n++) y = fmaf(h[n], Cv[n], y);

            float z = __half2float(g_xzh[row * (size_t)(2 * DIN) + DIN + d]);
            float sz = z / (1.f + __expf(-z));
            g_gateh[row * DIN + d] = __float2half_rn(y * sz);
        }
    }

    if constexpr (!PASS2) {
        #pragma unroll
        for (int n = 0; n < NST; n += 4) {
            float4 vp = { P[n], P[n+1], P[n+2], P[n+3] };
            float4 vh = { h[n], h[n+1], h[n+2], h[n+3] };
            *(float4*)(g_P + sidx + n)    = vp;
            *(float4*)(g_hloc + sidx + n) = vh;
        }
    }
}

__global__ void scan_combine_kernel()
{
    int gid = blockIdx.x * blockDim.x + threadIdx.x;
    if (gid >= BSZ * DIN) return;
    size_t base = (size_t)gid * NCH * NST;
    float H[NST];
    #pragma unroll
    for (int n = 0; n < NST; n++) H[n] = 0.f;
    for (int c = 0; c < NCH; c++) {
        size_t idx = base + (size_t)c * NST;
        #pragma unroll
        for (int n = 0; n < NST; n += 4) {
            float4 v = { H[n], H[n+1], H[n+2], H[n+3] };
            *(float4*)(g_H0 + idx + n) = v;
        }
        #pragma unroll
        for (int n = 0; n < NST; n++)
            H[n] = fmaf(g_P[idx + n], H[n], g_hloc[idx + n]);
    }
}

// ---------------------------------------------------------------------------
// Launch
// ---------------------------------------------------------------------------
extern "C" void kernel_launch(void* const* d_in, const int* in_sizes, int n_in,
                              void* d_out, int out_size)
{
    const float* x       = (const float*)d_in[0];
    const float* w_norm  = (const float*)d_in[1];
    const float* b_norm  = (const float*)d_in[2];
    const float* w_in    = (const float*)d_in[3];
    const float* w_conv  = (const float*)d_in[4];
    const float* b_conv  = (const float*)d_in[5];
    const float* A_log   = (const float*)d_in[6];
    const float* w_b     = (const float*)d_in[7];
    const float* w_c     = (const float*)d_in[8];
    const float* w_delta = (const float*)d_in[9];
    const float* b_delta = (const float*)d_in[10];
    const float* D_param = (const float*)d_in[11];
    const float* w_out   = (const float*)d_in[12];
    float* out = (float*)d_out;

    cudaFuncSetAttribute(tc_gemm<2 * DIN, DM, 0, 0>,
                         cudaFuncAttributeMaxDynamicSharedMemorySize, GEMM_DSMEM);
    cudaFuncSetAttribute(tc_gemm<N2, DIN, 3, 1>,
                         cudaFuncAttributeMaxDynamicSharedMemorySize, GEMM_DSMEM);
    cudaFuncSetAttribute(tc_gemm<DM, DIN, 2, 2>,
                         cudaFuncAttributeMaxDynamicSharedMemorySize, GEMM_DSMEM);

    __half *wt_in, *wt_d2, *wt_o;
    cudaGetSymbolAddress((void**)&wt_in, g_wtin);
    cudaGetSymbolAddress((void**)&wt_d2, g_wtd2);
    cudaGetSymbolAddress((void**)&wt_o,  g_wto);

    // 0. weight prep
    transpose_h_kernel<<<dim3((2 * DIN) / 32, DM / 32), dim3(32, 8)>>>(w_in, wt_in, DM, 2 * DIN);
    transpose_h_kernel<<<dim3(DIN / 32, DIN / 32), dim3(32, 8)>>>(w_delta, wt_d2, DIN, DIN);
    prep_wbc_kernel<<<DIN / 256, 256>>>(w_b, w_c);
    transpose_h_kernel<<<dim3(DM / 32, DIN / 32), dim3(32, 8)>>>(w_out, wt_o, DIN, DM);

    // 1. LayerNorm (fp16 out)
    ln_kernel<<<ROWS, 256>>>(x, w_norm, b_norm);

    // 2. xz = xn @ w_in  (fp16 out)
    tc_gemm<2 * DIN, DM, 0, 0>
        <<<dim3((2 * DIN) / 128, ROWS / 128), 128, GEMM_DSMEM>>>(wt_in, nullptr, nullptr, nullptr);

    // 3. conv + silu -> uh (fp16)
    conv_silu_kernel<<<(ROWS * (DIN / 8)) / 256, 256>>>(w_conv, b_conv);

    // 4. combined: delta = softplus(u@w_delta + b), Bseq, Cseq
    tc_gemm<N2, DIN, 3, 1>
        <<<dim3(N2 / 128, ROWS / 128), 128, GEMM_DSMEM>>>(wt_d2, b_delta, nullptr, nullptr);

    // 5. chunked selective scan
    scan_kernel<false><<<(BSZ * DIN * NCH) / 256, 256>>>(A_log, D_param);
    scan_combine_kernel<<<(BSZ * DIN) / 256, 256>>>();
    scan_kernel<true><<<(BSZ * DIN * NCH) / 256, 256>>>(A_log, D_param);

    // 6. out = gate @ w_out + residual
    tc_gemm<DM, DIN, 2, 2>
        <<<dim3(DM / 128, ROWS / 128), 128, GEMM_DSMEM>>>(wt_o, nullptr, x, out);
}